// round 4
// baseline (speedup 1.0000x reference)
#include <cuda_runtime.h>
#include <math.h>
#include <stdint.h>

// Problem constants
#define Bb   2
#define Nn   1024
#define Cc   1024
#define Hh   16
#define Dd   64
#define BLKc 8
#define NBc  128
#define TOPKc 7
#define BHc  (Bb*Hh)          // 32
#define NCHUNK 16             // kv accumulation chunks
#define CHLEN (Nn/NCHUNK)     // 64

// ---------------- scratch (device globals; no allocation) ----------------
__device__ __align__(16) float g_qkv [Bb*Nn*3*Cc];        // (B,N,3C)
__device__ __align__(16) float g_q   [BHc*Nn*Dd];
__device__ __align__(16) float g_k   [BHc*Nn*Dd];
__device__ __align__(16) float g_v   [BHc*Nn*Dd];
__device__ __align__(16) float g_pq  [BHc*Nn*Dd];         // phi_q
__device__ __align__(16) float g_pk  [BHc*Nn*Dd];         // phi_k
__device__ __align__(16) float g_kcmp[BHc*NBc*Dd];
__device__               int   g_topk[BHc*Nn*TOPKc];
__device__ __align__(16) float g_kvp [NCHUNK*BHc*Dd*Dd];  // partial kv
__device__ __align__(16) float g_zp  [NCHUNK*BHc*Dd];     // partial z
__device__ __align__(16) float g_kv  [BHc*Dd*Dd];
__device__ __align__(16) float g_z   [BHc*Dd];
__device__ __align__(16) float g_attn[Bb*Nn*Cc];          // (B,N,C) pre-proj

// =============== tf32 tensor-core GEMM (3xTF32 for fp32 accuracy) ========
#define GBM 128
#define GBN 64
#define GBK 16
#define ASTR 136
#define BSTR 72

__device__ __forceinline__ uint32_t f2tf32(float x) {
    uint32_t r;
    asm("cvt.rna.tf32.f32 %0, %1;" : "=r"(r) : "f"(x));
    return r;
}

__device__ __forceinline__ void mma_tf32(float* d, const uint32_t* a, const uint32_t* b) {
    asm volatile(
        "mma.sync.aligned.m16n8k8.row.col.f32.tf32.tf32.f32 "
        "{%0,%1,%2,%3}, {%4,%5,%6,%7}, {%8,%9}, {%0,%1,%2,%3};"
        : "+f"(d[0]), "+f"(d[1]), "+f"(d[2]), "+f"(d[3])
        : "r"(a[0]), "r"(a[1]), "r"(a[2]), "r"(a[3]), "r"(b[0]), "r"(b[1]));
}

__global__ __launch_bounds__(256) void gemm_tf32_kernel(
    const float* __restrict__ A, const float* __restrict__ B,
    const float* __restrict__ bias, float* __restrict__ C,
    int M, int N, int K)
{
    __shared__ float As[2][GBK*ASTR];
    __shared__ float Bs[2][GBK*BSTR];
    const int tid  = threadIdx.x;
    const int lane = tid & 31;
    const int warp = tid >> 5;
    const int warpM = warp & 3;
    const int warpN = warp >> 2;
    const int g  = lane >> 2;
    const int tq = lane & 3;
    const int bm = blockIdx.y * GBM;
    const int bn = blockIdx.x * GBN;

    const int aR  = tid >> 1;
    const int aKq = (tid & 1) * 2;
    const int bK  = tid >> 4;
    const int bN4 = (tid & 15) * 4;

    float acc[2][4][4];
#pragma unroll
    for (int mf = 0; mf < 2; mf++)
#pragma unroll
        for (int nf = 0; nf < 4; nf++)
#pragma unroll
            for (int r = 0; r < 4; r++) acc[mf][nf][r] = 0.f;

    const int nIter = K / GBK;

    {
        float4 a0 = *reinterpret_cast<const float4*>(A + (size_t)(bm + aR) * K + (aKq + 0) * 4);
        float4 a1 = *reinterpret_cast<const float4*>(A + (size_t)(bm + aR) * K + (aKq + 1) * 4);
        float4 bv = *reinterpret_cast<const float4*>(B + (size_t)bK * N + bn + bN4);
        As[0][(aKq*4 + 0)*ASTR + aR] = a0.x;
        As[0][(aKq*4 + 1)*ASTR + aR] = a0.y;
        As[0][(aKq*4 + 2)*ASTR + aR] = a0.z;
        As[0][(aKq*4 + 3)*ASTR + aR] = a0.w;
        As[0][(aKq*4 + 4)*ASTR + aR] = a1.x;
        As[0][(aKq*4 + 5)*ASTR + aR] = a1.y;
        As[0][(aKq*4 + 6)*ASTR + aR] = a1.z;
        As[0][(aKq*4 + 7)*ASTR + aR] = a1.w;
        *reinterpret_cast<float4*>(&Bs[0][bK*BSTR + bN4]) = bv;
    }
    __syncthreads();

    for (int it = 0; it < nIter; it++) {
        const int buf = it & 1;
        float4 na0, na1, nb;
        const bool more = (it + 1 < nIter);
        if (more) {
            int k0 = (it + 1) * GBK;
            na0 = *reinterpret_cast<const float4*>(A + (size_t)(bm + aR) * K + k0 + (aKq + 0) * 4);
            na1 = *reinterpret_cast<const float4*>(A + (size_t)(bm + aR) * K + k0 + (aKq + 1) * 4);
            nb  = *reinterpret_cast<const float4*>(B + (size_t)(k0 + bK) * N + bn + bN4);
        }

        const float* as = As[buf];
        const float* bs = Bs[buf];
#pragma unroll
        for (int ks = 0; ks < 2; ks++) {
            const int kb = ks * 8;
            uint32_t ahi[2][4], alo[2][4];
#pragma unroll
            for (int mf = 0; mf < 2; mf++) {
                const int m = warpM * 32 + mf * 16 + g;
                const float* p = as + (kb + tq) * ASTR + m;
                float v0 = p[0];
                float v1 = p[8];
                float v2 = p[4*ASTR];
                float v3 = p[4*ASTR + 8];
                ahi[mf][0] = f2tf32(v0); alo[mf][0] = f2tf32(v0 - __uint_as_float(ahi[mf][0]));
                ahi[mf][1] = f2tf32(v1); alo[mf][1] = f2tf32(v1 - __uint_as_float(ahi[mf][1]));
                ahi[mf][2] = f2tf32(v2); alo[mf][2] = f2tf32(v2 - __uint_as_float(ahi[mf][2]));
                ahi[mf][3] = f2tf32(v3); alo[mf][3] = f2tf32(v3 - __uint_as_float(ahi[mf][3]));
            }
            uint32_t bhi[4][2], blo[4][2];
#pragma unroll
            for (int nf = 0; nf < 4; nf++) {
                const int n = warpN * 32 + nf * 8 + g;
                const float* p = bs + (kb + tq) * BSTR + n;
                float v0 = p[0];
                float v1 = p[4*BSTR];
                bhi[nf][0] = f2tf32(v0); blo[nf][0] = f2tf32(v0 - __uint_as_float(bhi[nf][0]));
                bhi[nf][1] = f2tf32(v1); blo[nf][1] = f2tf32(v1 - __uint_as_float(bhi[nf][1]));
            }
#pragma unroll
            for (int mf = 0; mf < 2; mf++)
#pragma unroll
                for (int nf = 0; nf < 4; nf++) mma_tf32(acc[mf][nf], ahi[mf], bhi[nf]);
#pragma unroll
            for (int mf = 0; mf < 2; mf++)
#pragma unroll
                for (int nf = 0; nf < 4; nf++) mma_tf32(acc[mf][nf], alo[mf], bhi[nf]);
#pragma unroll
            for (int mf = 0; mf < 2; mf++)
#pragma unroll
                for (int nf = 0; nf < 4; nf++) mma_tf32(acc[mf][nf], ahi[mf], blo[nf]);
        }

        if (more) {
            const int nbuf = buf ^ 1;
            As[nbuf][(aKq*4 + 0)*ASTR + aR] = na0.x;
            As[nbuf][(aKq*4 + 1)*ASTR + aR] = na0.y;
            As[nbuf][(aKq*4 + 2)*ASTR + aR] = na0.z;
            As[nbuf][(aKq*4 + 3)*ASTR + aR] = na0.w;
            As[nbuf][(aKq*4 + 4)*ASTR + aR] = na1.x;
            As[nbuf][(aKq*4 + 5)*ASTR + aR] = na1.y;
            As[nbuf][(aKq*4 + 6)*ASTR + aR] = na1.z;
            As[nbuf][(aKq*4 + 7)*ASTR + aR] = na1.w;
            *reinterpret_cast<float4*>(&Bs[nbuf][bK*BSTR + bN4]) = nb;
        }
        __syncthreads();
    }

#pragma unroll
    for (int mf = 0; mf < 2; mf++) {
#pragma unroll
        for (int nf = 0; nf < 4; nf++) {
            const int r0 = bm + warpM * 32 + mf * 16 + g;
            const int c0 = bn + warpN * 32 + nf * 8 + tq * 2;
            float2 bv = *reinterpret_cast<const float2*>(bias + c0);
            float2 o0 = make_float2(acc[mf][nf][0] + bv.x, acc[mf][nf][1] + bv.y);
            float2 o1 = make_float2(acc[mf][nf][2] + bv.x, acc[mf][nf][3] + bv.y);
            *reinterpret_cast<float2*>(C + (size_t)r0 * N + c0)       = o0;
            *reinterpret_cast<float2*>(C + (size_t)(r0 + 8) * N + c0) = o1;
        }
    }
}

// ------------- LayerNorm(q,k) + phi softmax + v copy, per (b,n) ----------
__global__ __launch_bounds__(512) void ln_phi_kernel(
    const float* __restrict__ qw, const float* __restrict__ qb,
    const float* __restrict__ kw, const float* __restrict__ kb)
{
    int bn = blockIdx.x;
    int b = bn / Nn, n = bn % Nn;
    int h = threadIdx.x >> 5;
    int lane = threadIdx.x & 31;
    const float* row = g_qkv + (size_t)bn * (3*Cc);
    int d0 = lane, d1 = lane + 32;
    size_t obase = ((size_t)(b*Hh + h) * Nn + n) * Dd;

    // ---- q ----
    {
        float v0 = row[h*Dd + d0], v1 = row[h*Dd + d1];
        float s = v0 + v1;
#pragma unroll
        for (int o = 16; o; o >>= 1) s += __shfl_xor_sync(~0u, s, o);
        float m = s * (1.f/64.f);
        float a0 = v0 - m, a1 = v1 - m;
        float vs = a0*a0 + a1*a1;
#pragma unroll
        for (int o = 16; o; o >>= 1) vs += __shfl_xor_sync(~0u, vs, o);
        float r = rsqrtf(vs * (1.f/64.f) + 1e-6f);
        float y0 = a0*r*qw[d0] + qb[d0];
        float y1 = a1*r*qw[d1] + qb[d1];
        g_q[obase + d0] = y0; g_q[obase + d1] = y1;
        float mx = fmaxf(y0, y1);
#pragma unroll
        for (int o = 16; o; o >>= 1) mx = fmaxf(mx, __shfl_xor_sync(~0u, mx, o));
        float e0 = __expf(y0 - mx), e1 = __expf(y1 - mx);
        float se = e0 + e1;
#pragma unroll
        for (int o = 16; o; o >>= 1) se += __shfl_xor_sync(~0u, se, o);
        float inv = 1.f / se;
        g_pq[obase + d0] = e0*inv; g_pq[obase + d1] = e1*inv;
    }
    // ---- k ----
    {
        float v0 = row[Cc + h*Dd + d0], v1 = row[Cc + h*Dd + d1];
        float s = v0 + v1;
#pragma unroll
        for (int o = 16; o; o >>= 1) s += __shfl_xor_sync(~0u, s, o);
        float m = s * (1.f/64.f);
        float a0 = v0 - m, a1 = v1 - m;
        float vs = a0*a0 + a1*a1;
#pragma unroll
        for (int o = 16; o; o >>= 1) vs += __shfl_xor_sync(~0u, vs, o);
        float r = rsqrtf(vs * (1.f/64.f) + 1e-6f);
        float y0 = a0*r*kw[d0] + kb[d0];
        float y1 = a1*r*kw[d1] + kb[d1];
        g_k[obase + d0] = y0; g_k[obase + d1] = y1;
        float mx = fmaxf(y0, y1);
#pragma unroll
        for (int o = 16; o; o >>= 1) mx = fmaxf(mx, __shfl_xor_sync(~0u, mx, o));
        float e0 = __expf(y0 - mx), e1 = __expf(y1 - mx);
        float se = e0 + e1;
#pragma unroll
        for (int o = 16; o; o >>= 1) se += __shfl_xor_sync(~0u, se, o);
        float inv = 1.f / se;
        g_pk[obase + d0] = e0*inv; g_pk[obase + d1] = e1*inv;
    }
    // ---- v copy ----
    g_v[obase + d0] = row[2*Cc + h*Dd + d0];
    g_v[obase + d1] = row[2*Cc + h*Dd + d1];
}

// ------------- compressed keys: mean pool over BLK=8 ---------------------
__global__ __launch_bounds__(64) void kcmp_kernel()
{
    int bhm = blockIdx.x;            // B*H*NB
    int d = threadIdx.x;
    int bh = bhm / NBc, m = bhm % NBc;
    const float* kr = g_k + ((size_t)bh*Nn + m*BLKc) * Dd;
    float s = 0.f;
#pragma unroll
    for (int t = 0; t < BLKc; t++) s += kr[t*Dd + d];
    g_kcmp[(size_t)bhm*Dd + d] = s * (1.f/BLKc);
}

// ------------- kv/z partials (deterministic, no atomics) -----------------
__global__ __launch_bounds__(256) void kv_chunk_kernel()
{
    int bh = blockIdx.x;
    int ch = blockIdx.y;
    int tid = threadIdx.x;
    int e = tid & 63;
    int dg = tid >> 6;               // 0..3
    __shared__ float sh[4][128];
    float acc[16];
#pragma unroll
    for (int j = 0; j < 16; j++) acc[j] = 0.f;
    float zacc = 0.f;
    size_t base = (size_t)bh * Nn * Dd;
    const int lr = tid >> 6;
    const int lc = (tid & 63) * 2;
    for (int i0 = 0; i0 < CHLEN; i0 += 4) {
        __syncthreads();
        {
            int n = ch * CHLEN + i0 + lr;
            float2 val;
            if (lc < 64)
                val = *reinterpret_cast<const float2*>(g_pk + base + (size_t)n*Dd + lc);
            else
                val = *reinterpret_cast<const float2*>(g_v + base + (size_t)n*Dd + (lc - 64));
            sh[lr][lc]   = val.x;
            sh[lr][lc+1] = val.y;
        }
        __syncthreads();
#pragma unroll
        for (int r = 0; r < 4; r++) {
            float ve = sh[r][64 + e];
#pragma unroll
            for (int j = 0; j < 16; j++) acc[j] += sh[r][dg*16 + j] * ve;
            if (tid < 64) zacc += sh[r][tid];
        }
    }
    float* out = g_kvp + ((size_t)ch * BHc + bh) * (Dd*Dd);
#pragma unroll
    for (int j = 0; j < 16; j++) out[(dg*16 + j)*Dd + e] = acc[j];
    if (tid < 64) g_zp[((size_t)ch * BHc + bh) * Dd + tid] = zacc;
}

__global__ __launch_bounds__(256) void kv_reduce_kernel()
{
    int idx = blockIdx.x * 256 + threadIdx.x;
    const int KVN = BHc*Dd*Dd;
    const int ZN  = BHc*Dd;
    if (idx < KVN) {
        float s = 0.f;
#pragma unroll
        for (int c = 0; c < NCHUNK; c++) s += g_kvp[(size_t)c*KVN + idx];
        g_kv[idx] = s;
    } else if (idx < KVN + ZN) {
        int z = idx - KVN;
        float s = 0.f;
#pragma unroll
        for (int c = 0; c < NCHUNK; c++) s += g_zp[(size_t)c*ZN + z];
        g_z[z] = s;
    }
}

// ------------- router + top-7 v2 : smem-transposed kcmp ------------------
// grid = BH * (N/64), 256 threads = 8 warps; each warp does 8 queries.
#define KCSTR 132   // row stride (floats), 16B multiple, conflict-free LDS.128
__global__ __launch_bounds__(256) void router_topk_kernel()
{
    __shared__ float kct[Dd * KCSTR];   // [d][blk], 33.8KB
    int bh = blockIdx.x >> 4;           // Nn/64 = 16 query tiles
    int n0 = (blockIdx.x & 15) * 64;
    int tid = threadIdx.x;
    int warp = tid >> 5, lane = tid & 31;

    // transpose-load kcmp (coalesced global reads)
    const float* kc = g_kcmp + (size_t)bh * NBc * Dd;
#pragma unroll
    for (int i = 0; i < 32; i++) {
        int idx = tid + i * 256;        // 0..8191
        int blk = idx >> 6, d = idx & 63;
        kct[d * KCSTR + blk] = kc[idx];
    }
    __syncthreads();

    const float scale = 0.125f;
    const float NEGINF = -__int_as_float(0x7f800000);

    for (int qi = 0; qi < 8; qi++) {
        int n = n0 + warp * 8 + qi;
        const float* qrow = g_q + ((size_t)bh*Nn + n) * Dd;
        float q0 = qrow[lane], q1 = qrow[lane + 32];
        float s0 = 0.f, s1 = 0.f, s2 = 0.f, s3 = 0.f;
#pragma unroll
        for (int d = 0; d < 64; d++) {
            float qd = (d < 32) ? __shfl_sync(~0u, q0, d)
                                : __shfl_sync(~0u, q1, d - 32);
            float4 kv4 = *reinterpret_cast<const float4*>(&kct[d * KCSTR + lane * 4]);
            s0 += qd * kv4.x; s1 += qd * kv4.y;
            s2 += qd * kv4.z; s3 += qd * kv4.w;
        }
        s0 *= scale; s1 *= scale; s2 *= scale; s3 *= scale;

        int qidx = bh * Nn + n;
#pragma unroll
        for (int r = 0; r < TOPKc; r++) {
            float bv = s0; int bj = 0;
            if (s1 > bv) { bv = s1; bj = 1; }
            if (s2 > bv) { bv = s2; bj = 2; }
            if (s3 > bv) { bv = s3; bj = 3; }
            int bm = lane * 4 + bj;
#pragma unroll
            for (int o = 16; o; o >>= 1) {
                float ov = __shfl_xor_sync(~0u, bv, o);
                int   om = __shfl_xor_sync(~0u, bm, o);
                if (ov > bv || (ov == bv && om < bm)) { bv = ov; bm = om; }
            }
            if ((bm >> 2) == lane) {
                int j = bm & 3;
                if      (j == 0) s0 = NEGINF;
                else if (j == 1) s1 = NEGINF;
                else if (j == 2) s2 = NEGINF;
                else             s3 = NEGINF;
            }
            if (lane == 0) g_topk[(size_t)qidx*TOPKc + r] = bm;
        }
    }
}

// ------------- fused sparse softmax attention + linear branch ------------
__global__ __launch_bounds__(256) void attn_kernel()
{
    int bh = blockIdx.x / (Nn/8);
    int b = bh / Hh, h = bh % Hh;
    int n0 = (blockIdx.x % (Nn/8)) * 8;
    int warp = threadIdx.x >> 5;
    int lane = threadIdx.x & 31;
    int n = n0 + warp;
    __shared__ float sq [8][64];
    __shared__ float spq[8][64];
    __shared__ float sp [8][64];
    __shared__ int   sblk[8][8];

    size_t qb = ((size_t)bh*Nn + n) * Dd;
    {
        float2 a = *reinterpret_cast<const float2*>(g_q  + qb + lane*2);
        float2 c = *reinterpret_cast<const float2*>(g_pq + qb + lane*2);
        sq [warp][lane*2] = a.x; sq [warp][lane*2+1] = a.y;
        spq[warp][lane*2] = c.x; spq[warp][lane*2+1] = c.y;
    }
    if (lane < TOPKc) sblk[warp][lane] = g_topk[((size_t)bh*Nn + n)*TOPKc + lane];
    __syncwarp();

    const float scale = 0.125f;
    const int NSEL = TOPKc * BLKc;   // 56
    const float NEGINF = -__int_as_float(0x7f800000);
    const float4* sq4 = reinterpret_cast<const float4*>(sq[warp]);

    float l0, l1;
    {
        int s = lane;
        int tok = sblk[warp][s >> 3] * BLKc + (s & 7);
        const float4* kr4 = reinterpret_cast<const float4*>(
            g_k + ((size_t)bh*Nn + tok) * Dd);
        float a = 0.f;
#pragma unroll
        for (int t = 0; t < 16; t++) {
            float4 qv = sq4[t];
            float4 kv = __ldg(kr4 + t);
            a += qv.x*kv.x + qv.y*kv.y + qv.z*kv.z + qv.w*kv.w;
        }
        l0 = a * scale;
    }
    {
        int s = lane + 32;
        if (s < NSEL) {
            int tok = sblk[warp][s >> 3] * BLKc + (s & 7);
            const float4* kr4 = reinterpret_cast<const float4*>(
                g_k + ((size_t)bh*Nn + tok) * Dd);
            float a = 0.f;
#pragma unroll
            for (int t = 0; t < 16; t++) {
                float4 qv = sq4[t];
                float4 kv = __ldg(kr4 + t);
                a += qv.x*kv.x + qv.y*kv.y + qv.z*kv.z + qv.w*kv.w;
            }
            l1 = a * scale;
        } else l1 = NEGINF;
    }
    float mx = fmaxf(l0, l1);
#pragma unroll
    for (int o = 16; o; o >>= 1) mx = fmaxf(mx, __shfl_xor_sync(~0u, mx, o));
    float e0 = __expf(l0 - mx);
    float e1 = (lane + 32 < NSEL) ? __expf(l1 - mx) : 0.f;
    float se = e0 + e1;
#pragma unroll
    for (int o = 16; o; o >>= 1) se += __shfl_xor_sync(~0u, se, o);
    float inv = 1.f / se;
    sp[warp][lane]      = e0 * inv;
    sp[warp][lane + 32] = e1 * inv;
    __syncwarp();

    int d0 = lane, d1 = lane + 32;
    float a0 = 0.f, a1 = 0.f;
#pragma unroll
    for (int s = 0; s < NSEL; s++) {
        int tok = sblk[warp][s >> 3] * BLKc + (s & 7);
        const float* vr = g_v + ((size_t)bh*Nn + tok) * Dd;
        float p = sp[warp][s];
        a0 += p * vr[d0];
        a1 += p * vr[d1];
    }

    const float* zr = g_z + (size_t)bh * Dd;
    float t = spq[warp][d0]*zr[d0] + spq[warp][d1]*zr[d1];
#pragma unroll
    for (int o = 16; o; o >>= 1) t += __shfl_xor_sync(~0u, t, o);
    float inv_den = 1.f / (t + 1e-6f);
    const float* kvm = g_kv + (size_t)bh * Dd * Dd;
    float n0a = 0.f, n1a = 0.f;
#pragma unroll
    for (int e = 0; e < 64; e++) {
        float pe = spq[warp][e];
        n0a += pe * kvm[e*Dd + d0];
        n1a += pe * kvm[e*Dd + d1];
    }
    size_t ob = ((size_t)(b*Nn + n)) * Cc + h*Dd;
    g_attn[ob + d0] = a0 + n0a * inv_den;
    g_attn[ob + d1] = a1 + n1a * inv_den;
}

// ---------------------------------------------------------------------------
extern "C" void kernel_launch(void* const* d_in, const int* in_sizes, int n_in,
                              void* d_out, int out_size)
{
    const float* x      = (const float*)d_in[0];
    const float* w_qkv  = (const float*)d_in[1];
    const float* b_qkv  = (const float*)d_in[2];
    const float* qw     = (const float*)d_in[3];
    const float* qb     = (const float*)d_in[4];
    const float* kw     = (const float*)d_in[5];
    const float* kb     = (const float*)d_in[6];
    const float* w_proj = (const float*)d_in[7];
    const float* b_proj = (const float*)d_in[8];
    float* out = (float*)d_out;

    void *p_qkv = nullptr, *p_attn = nullptr;
    cudaGetSymbolAddress(&p_qkv,  g_qkv);
    cudaGetSymbolAddress(&p_attn, g_attn);

    // 1) qkv = x @ w_qkv + b_qkv
    {
        dim3 grid(3*Cc/GBN, Bb*Nn/GBM);
        gemm_tf32_kernel<<<grid, 256>>>(x, w_qkv, b_qkv, (float*)p_qkv,
                                        Bb*Nn, 3*Cc, Cc);
    }
    // 2) layernorm + phi + split heads
    ln_phi_kernel<<<Bb*Nn, 512>>>(qw, qb, kw, kb);
    // 3) compressed keys
    kcmp_kernel<<<BHc*NBc, 64>>>();
    // 4) kv / z
    {
        dim3 grid(BHc, NCHUNK);
        kv_chunk_kernel<<<grid, 256>>>();
        int total = BHc*Dd*Dd + BHc*Dd;
        kv_reduce_kernel<<<(total + 255)/256, 256>>>();
    }
    // 5) router + topk
    router_topk_kernel<<<BHc*(Nn/64), 256>>>();
    // 6) sparse + linear attention
    attn_kernel<<<BHc*(Nn/8), 256>>>();
    // 7) out = attn @ w_proj + b_proj
    {
        dim3 grid(Cc/GBN, Bb*Nn/GBM);
        gemm_tf32_kernel<<<grid, 256>>>((const float*)p_attn, w_proj, b_proj,
                                        out, Bb*Nn, Cc, Cc);
    }
    (void)in_sizes; (void)n_in; (void)out_size;
}

// round 5
// speedup vs baseline: 1.0014x; 1.0014x over previous
#include <cuda_runtime.h>
#include <math.h>
#include <stdint.h>

// Problem constants
#define Bb   2
#define Nn   1024
#define Cc   1024
#define Hh   16
#define Dd   64
#define BLKc 8
#define NBc  128
#define TOPKc 7
#define BHc  (Bb*Hh)          // 32
#define NCHUNK 16             // kv accumulation chunks
#define CHLEN (Nn/NCHUNK)     // 64

// ---------------- scratch (device globals; no allocation) ----------------
__device__ __align__(16) float g_qkv [Bb*Nn*3*Cc];        // (B,N,3C)
__device__ __align__(16) float g_q   [BHc*Nn*Dd];
__device__ __align__(16) float g_k   [BHc*Nn*Dd];
__device__ __align__(16) float g_v   [BHc*Nn*Dd];
__device__ __align__(16) float g_pq  [BHc*Nn*Dd];         // phi_q
__device__ __align__(16) float g_pk  [BHc*Nn*Dd];         // phi_k
__device__ __align__(16) float g_kcmp[BHc*NBc*Dd];
__device__               int   g_topk[BHc*Nn*TOPKc];
__device__ __align__(16) float g_kvp [NCHUNK*BHc*Dd*Dd];  // partial kv
__device__ __align__(16) float g_zp  [NCHUNK*BHc*Dd];     // partial z
__device__ __align__(16) float g_kv  [BHc*Dd*Dd];
__device__ __align__(16) float g_z   [BHc*Dd];
__device__ __align__(16) float g_attn[Bb*Nn*Cc];          // (B,N,C) pre-proj

// =============== tf32 tensor-core GEMM (3xTF32 for fp32 accuracy) ========
#define GBM 128
#define GBN 64
#define GBK 16
#define ASTR 136
#define BSTR 72

__device__ __forceinline__ uint32_t f2tf32(float x) {
    uint32_t r;
    asm("cvt.rna.tf32.f32 %0, %1;" : "=r"(r) : "f"(x));
    return r;
}

__device__ __forceinline__ void mma_tf32(float* d, const uint32_t* a, const uint32_t* b) {
    asm volatile(
        "mma.sync.aligned.m16n8k8.row.col.f32.tf32.tf32.f32 "
        "{%0,%1,%2,%3}, {%4,%5,%6,%7}, {%8,%9}, {%0,%1,%2,%3};"
        : "+f"(d[0]), "+f"(d[1]), "+f"(d[2]), "+f"(d[3])
        : "r"(a[0]), "r"(a[1]), "r"(a[2]), "r"(a[3]), "r"(b[0]), "r"(b[1]));
}

__global__ __launch_bounds__(256) void gemm_tf32_kernel(
    const float* __restrict__ A, const float* __restrict__ B,
    const float* __restrict__ bias, float* __restrict__ C,
    int M, int N, int K)
{
    __shared__ float As[2][GBK*ASTR];
    __shared__ float Bs[2][GBK*BSTR];
    const int tid  = threadIdx.x;
    const int lane = tid & 31;
    const int warp = tid >> 5;
    const int warpM = warp & 3;
    const int warpN = warp >> 2;
    const int g  = lane >> 2;
    const int tq = lane & 3;
    const int bm = blockIdx.y * GBM;
    const int bn = blockIdx.x * GBN;

    const int aR  = tid >> 1;
    const int aKq = (tid & 1) * 2;
    const int bK  = tid >> 4;
    const int bN4 = (tid & 15) * 4;

    float acc[2][4][4];
#pragma unroll
    for (int mf = 0; mf < 2; mf++)
#pragma unroll
        for (int nf = 0; nf < 4; nf++)
#pragma unroll
            for (int r = 0; r < 4; r++) acc[mf][nf][r] = 0.f;

    const int nIter = K / GBK;

    {
        float4 a0 = *reinterpret_cast<const float4*>(A + (size_t)(bm + aR) * K + (aKq + 0) * 4);
        float4 a1 = *reinterpret_cast<const float4*>(A + (size_t)(bm + aR) * K + (aKq + 1) * 4);
        float4 bv = *reinterpret_cast<const float4*>(B + (size_t)bK * N + bn + bN4);
        As[0][(aKq*4 + 0)*ASTR + aR] = a0.x;
        As[0][(aKq*4 + 1)*ASTR + aR] = a0.y;
        As[0][(aKq*4 + 2)*ASTR + aR] = a0.z;
        As[0][(aKq*4 + 3)*ASTR + aR] = a0.w;
        As[0][(aKq*4 + 4)*ASTR + aR] = a1.x;
        As[0][(aKq*4 + 5)*ASTR + aR] = a1.y;
        As[0][(aKq*4 + 6)*ASTR + aR] = a1.z;
        As[0][(aKq*4 + 7)*ASTR + aR] = a1.w;
        *reinterpret_cast<float4*>(&Bs[0][bK*BSTR + bN4]) = bv;
    }
    __syncthreads();

    for (int it = 0; it < nIter; it++) {
        const int buf = it & 1;
        float4 na0, na1, nb;
        const bool more = (it + 1 < nIter);
        if (more) {
            int k0 = (it + 1) * GBK;
            na0 = *reinterpret_cast<const float4*>(A + (size_t)(bm + aR) * K + k0 + (aKq + 0) * 4);
            na1 = *reinterpret_cast<const float4*>(A + (size_t)(bm + aR) * K + k0 + (aKq + 1) * 4);
            nb  = *reinterpret_cast<const float4*>(B + (size_t)(k0 + bK) * N + bn + bN4);
        }

        const float* as = As[buf];
        const float* bs = Bs[buf];
#pragma unroll
        for (int ks = 0; ks < 2; ks++) {
            const int kb = ks * 8;
            uint32_t ahi[2][4], alo[2][4];
#pragma unroll
            for (int mf = 0; mf < 2; mf++) {
                const int m = warpM * 32 + mf * 16 + g;
                const float* p = as + (kb + tq) * ASTR + m;
                float v0 = p[0];
                float v1 = p[8];
                float v2 = p[4*ASTR];
                float v3 = p[4*ASTR + 8];
                ahi[mf][0] = f2tf32(v0); alo[mf][0] = f2tf32(v0 - __uint_as_float(ahi[mf][0]));
                ahi[mf][1] = f2tf32(v1); alo[mf][1] = f2tf32(v1 - __uint_as_float(ahi[mf][1]));
                ahi[mf][2] = f2tf32(v2); alo[mf][2] = f2tf32(v2 - __uint_as_float(ahi[mf][2]));
                ahi[mf][3] = f2tf32(v3); alo[mf][3] = f2tf32(v3 - __uint_as_float(ahi[mf][3]));
            }
            uint32_t bhi[4][2], blo[4][2];
#pragma unroll
            for (int nf = 0; nf < 4; nf++) {
                const int n = warpN * 32 + nf * 8 + g;
                const float* p = bs + (kb + tq) * BSTR + n;
                float v0 = p[0];
                float v1 = p[4*BSTR];
                bhi[nf][0] = f2tf32(v0); blo[nf][0] = f2tf32(v0 - __uint_as_float(bhi[nf][0]));
                bhi[nf][1] = f2tf32(v1); blo[nf][1] = f2tf32(v1 - __uint_as_float(bhi[nf][1]));
            }
#pragma unroll
            for (int mf = 0; mf < 2; mf++)
#pragma unroll
                for (int nf = 0; nf < 4; nf++) mma_tf32(acc[mf][nf], ahi[mf], bhi[nf]);
#pragma unroll
            for (int mf = 0; mf < 2; mf++)
#pragma unroll
                for (int nf = 0; nf < 4; nf++) mma_tf32(acc[mf][nf], alo[mf], bhi[nf]);
#pragma unroll
            for (int mf = 0; mf < 2; mf++)
#pragma unroll
                for (int nf = 0; nf < 4; nf++) mma_tf32(acc[mf][nf], ahi[mf], blo[nf]);
        }

        if (more) {
            const int nbuf = buf ^ 1;
            As[nbuf][(aKq*4 + 0)*ASTR + aR] = na0.x;
            As[nbuf][(aKq*4 + 1)*ASTR + aR] = na0.y;
            As[nbuf][(aKq*4 + 2)*ASTR + aR] = na0.z;
            As[nbuf][(aKq*4 + 3)*ASTR + aR] = na0.w;
            As[nbuf][(aKq*4 + 4)*ASTR + aR] = na1.x;
            As[nbuf][(aKq*4 + 5)*ASTR + aR] = na1.y;
            As[nbuf][(aKq*4 + 6)*ASTR + aR] = na1.z;
            As[nbuf][(aKq*4 + 7)*ASTR + aR] = na1.w;
            *reinterpret_cast<float4*>(&Bs[nbuf][bK*BSTR + bN4]) = nb;
        }
        __syncthreads();
    }

#pragma unroll
    for (int mf = 0; mf < 2; mf++) {
#pragma unroll
        for (int nf = 0; nf < 4; nf++) {
            const int r0 = bm + warpM * 32 + mf * 16 + g;
            const int c0 = bn + warpN * 32 + nf * 8 + tq * 2;
            float2 bv = *reinterpret_cast<const float2*>(bias + c0);
            float2 o0 = make_float2(acc[mf][nf][0] + bv.x, acc[mf][nf][1] + bv.y);
            float2 o1 = make_float2(acc[mf][nf][2] + bv.x, acc[mf][nf][3] + bv.y);
            *reinterpret_cast<float2*>(C + (size_t)r0 * N + c0)       = o0;
            *reinterpret_cast<float2*>(C + (size_t)(r0 + 8) * N + c0) = o1;
        }
    }
}

// ------------- LayerNorm(q,k) + phi softmax + v copy, per (b,n) ----------
__global__ __launch_bounds__(512) void ln_phi_kernel(
    const float* __restrict__ qw, const float* __restrict__ qb,
    const float* __restrict__ kw, const float* __restrict__ kb)
{
    int bn = blockIdx.x;
    int b = bn / Nn, n = bn % Nn;
    int h = threadIdx.x >> 5;
    int lane = threadIdx.x & 31;
    const float* row = g_qkv + (size_t)bn * (3*Cc);
    int d0 = lane, d1 = lane + 32;
    size_t obase = ((size_t)(b*Hh + h) * Nn + n) * Dd;

    // ---- q ----
    {
        float v0 = row[h*Dd + d0], v1 = row[h*Dd + d1];
        float s = v0 + v1;
#pragma unroll
        for (int o = 16; o; o >>= 1) s += __shfl_xor_sync(~0u, s, o);
        float m = s * (1.f/64.f);
        float a0 = v0 - m, a1 = v1 - m;
        float vs = a0*a0 + a1*a1;
#pragma unroll
        for (int o = 16; o; o >>= 1) vs += __shfl_xor_sync(~0u, vs, o);
        float r = rsqrtf(vs * (1.f/64.f) + 1e-6f);
        float y0 = a0*r*qw[d0] + qb[d0];
        float y1 = a1*r*qw[d1] + qb[d1];
        g_q[obase + d0] = y0; g_q[obase + d1] = y1;
        float mx = fmaxf(y0, y1);
#pragma unroll
        for (int o = 16; o; o >>= 1) mx = fmaxf(mx, __shfl_xor_sync(~0u, mx, o));
        float e0 = __expf(y0 - mx), e1 = __expf(y1 - mx);
        float se = e0 + e1;
#pragma unroll
        for (int o = 16; o; o >>= 1) se += __shfl_xor_sync(~0u, se, o);
        float inv = 1.f / se;
        g_pq[obase + d0] = e0*inv; g_pq[obase + d1] = e1*inv;
    }
    // ---- k ----
    {
        float v0 = row[Cc + h*Dd + d0], v1 = row[Cc + h*Dd + d1];
        float s = v0 + v1;
#pragma unroll
        for (int o = 16; o; o >>= 1) s += __shfl_xor_sync(~0u, s, o);
        float m = s * (1.f/64.f);
        float a0 = v0 - m, a1 = v1 - m;
        float vs = a0*a0 + a1*a1;
#pragma unroll
        for (int o = 16; o; o >>= 1) vs += __shfl_xor_sync(~0u, vs, o);
        float r = rsqrtf(vs * (1.f/64.f) + 1e-6f);
        float y0 = a0*r*kw[d0] + kb[d0];
        float y1 = a1*r*kw[d1] + kb[d1];
        g_k[obase + d0] = y0; g_k[obase + d1] = y1;
        float mx = fmaxf(y0, y1);
#pragma unroll
        for (int o = 16; o; o >>= 1) mx = fmaxf(mx, __shfl_xor_sync(~0u, mx, o));
        float e0 = __expf(y0 - mx), e1 = __expf(y1 - mx);
        float se = e0 + e1;
#pragma unroll
        for (int o = 16; o; o >>= 1) se += __shfl_xor_sync(~0u, se, o);
        float inv = 1.f / se;
        g_pk[obase + d0] = e0*inv; g_pk[obase + d1] = e1*inv;
    }
    // ---- v copy ----
    g_v[obase + d0] = row[2*Cc + h*Dd + d0];
    g_v[obase + d1] = row[2*Cc + h*Dd + d1];
}

// ------------- compressed keys: mean pool over BLK=8 ---------------------
__global__ __launch_bounds__(64) void kcmp_kernel()
{
    int bhm = blockIdx.x;            // B*H*NB
    int d = threadIdx.x;
    int bh = bhm / NBc, m = bhm % NBc;
    const float* kr = g_k + ((size_t)bh*Nn + m*BLKc) * Dd;
    float s = 0.f;
#pragma unroll
    for (int t = 0; t < BLKc; t++) s += kr[t*Dd + d];
    g_kcmp[(size_t)bhm*Dd + d] = s * (1.f/BLKc);
}

// ------------- kv/z partials (deterministic, no atomics) -----------------
__global__ __launch_bounds__(256) void kv_chunk_kernel()
{
    int bh = blockIdx.x;
    int ch = blockIdx.y;
    int tid = threadIdx.x;
    int e = tid & 63;
    int dg = tid >> 6;               // 0..3
    __shared__ float sh[4][128];
    float acc[16];
#pragma unroll
    for (int j = 0; j < 16; j++) acc[j] = 0.f;
    float zacc = 0.f;
    size_t base = (size_t)bh * Nn * Dd;
    const int lr = tid >> 6;
    const int lc = (tid & 63) * 2;
    for (int i0 = 0; i0 < CHLEN; i0 += 4) {
        __syncthreads();
        {
            int n = ch * CHLEN + i0 + lr;
            float2 val;
            if (lc < 64)
                val = *reinterpret_cast<const float2*>(g_pk + base + (size_t)n*Dd + lc);
            else
                val = *reinterpret_cast<const float2*>(g_v + base + (size_t)n*Dd + (lc - 64));
            sh[lr][lc]   = val.x;
            sh[lr][lc+1] = val.y;
        }
        __syncthreads();
#pragma unroll
        for (int r = 0; r < 4; r++) {
            float ve = sh[r][64 + e];
#pragma unroll
            for (int j = 0; j < 16; j++) acc[j] += sh[r][dg*16 + j] * ve;
            if (tid < 64) zacc += sh[r][tid];
        }
    }
    float* out = g_kvp + ((size_t)ch * BHc + bh) * (Dd*Dd);
#pragma unroll
    for (int j = 0; j < 16; j++) out[(dg*16 + j)*Dd + e] = acc[j];
    if (tid < 64) g_zp[((size_t)ch * BHc + bh) * Dd + tid] = zacc;
}

__global__ __launch_bounds__(256) void kv_reduce_kernel()
{
    int idx = blockIdx.x * 256 + threadIdx.x;
    const int KVN = BHc*Dd*Dd;
    const int ZN  = BHc*Dd;
    if (idx < KVN) {
        float s = 0.f;
#pragma unroll
        for (int c = 0; c < NCHUNK; c++) s += g_kvp[(size_t)c*KVN + idx];
        g_kv[idx] = s;
    } else if (idx < KVN + ZN) {
        int z = idx - KVN;
        float s = 0.f;
#pragma unroll
        for (int c = 0; c < NCHUNK; c++) s += g_zp[(size_t)c*ZN + z];
        g_z[z] = s;
    }
}

// ------------- router + top-7 v2 : smem-transposed kcmp ------------------
// grid = BH * (N/64), 256 threads = 8 warps; each warp does 8 queries.
#define KCSTR 132   // row stride (floats), 16B multiple, conflict-free LDS.128
__global__ __launch_bounds__(256) void router_topk_kernel()
{
    __shared__ float kct[Dd * KCSTR];   // [d][blk], 33.8KB
    int bh = blockIdx.x >> 4;           // Nn/64 = 16 query tiles
    int n0 = (blockIdx.x & 15) * 64;
    int tid = threadIdx.x;
    int warp = tid >> 5, lane = tid & 31;

    // transpose-load kcmp (coalesced global reads)
    const float* kc = g_kcmp + (size_t)bh * NBc * Dd;
#pragma unroll
    for (int i = 0; i < 32; i++) {
        int idx = tid + i * 256;        // 0..8191
        int blk = idx >> 6, d = idx & 63;
        kct[d * KCSTR + blk] = kc[idx];
    }
    __syncthreads();

    const float scale = 0.125f;
    const float NEGINF = -__int_as_float(0x7f800000);

    for (int qi = 0; qi < 8; qi++) {
        int n = n0 + warp * 8 + qi;
        const float* qrow = g_q + ((size_t)bh*Nn + n) * Dd;
        float q0 = qrow[lane], q1 = qrow[lane + 32];
        float s0 = 0.f, s1 = 0.f, s2 = 0.f, s3 = 0.f;
#pragma unroll
        for (int d = 0; d < 64; d++) {
            float qd = (d < 32) ? __shfl_sync(~0u, q0, d)
                                : __shfl_sync(~0u, q1, d - 32);
            float4 kv4 = *reinterpret_cast<const float4*>(&kct[d * KCSTR + lane * 4]);
            s0 += qd * kv4.x; s1 += qd * kv4.y;
            s2 += qd * kv4.z; s3 += qd * kv4.w;
        }
        s0 *= scale; s1 *= scale; s2 *= scale; s3 *= scale;

        int qidx = bh * Nn + n;
#pragma unroll
        for (int r = 0; r < TOPKc; r++) {
            float bv = s0; int bj = 0;
            if (s1 > bv) { bv = s1; bj = 1; }
            if (s2 > bv) { bv = s2; bj = 2; }
            if (s3 > bv) { bv = s3; bj = 3; }
            int bm = lane * 4 + bj;
#pragma unroll
            for (int o = 16; o; o >>= 1) {
                float ov = __shfl_xor_sync(~0u, bv, o);
                int   om = __shfl_xor_sync(~0u, bm, o);
                if (ov > bv || (ov == bv && om < bm)) { bv = ov; bm = om; }
            }
            if ((bm >> 2) == lane) {
                int j = bm & 3;
                if      (j == 0) s0 = NEGINF;
                else if (j == 1) s1 = NEGINF;
                else if (j == 2) s2 = NEGINF;
                else             s3 = NEGINF;
            }
            if (lane == 0) g_topk[(size_t)qidx*TOPKc + r] = bm;
        }
    }
}

// ------------- fused sparse softmax attention + linear branch ------------
__global__ __launch_bounds__(256) void attn_kernel()
{
    int bh = blockIdx.x / (Nn/8);
    int b = bh / Hh, h = bh % Hh;
    int n0 = (blockIdx.x % (Nn/8)) * 8;
    int warp = threadIdx.x >> 5;
    int lane = threadIdx.x & 31;
    int n = n0 + warp;
    __shared__ float sq [8][64];
    __shared__ float spq[8][64];
    __shared__ float sp [8][64];
    __shared__ int   sblk[8][8];

    size_t qb = ((size_t)bh*Nn + n) * Dd;
    {
        float2 a = *reinterpret_cast<const float2*>(g_q  + qb + lane*2);
        float2 c = *reinterpret_cast<const float2*>(g_pq + qb + lane*2);
        sq [warp][lane*2] = a.x; sq [warp][lane*2+1] = a.y;
        spq[warp][lane*2] = c.x; spq[warp][lane*2+1] = c.y;
    }
    if (lane < TOPKc) sblk[warp][lane] = g_topk[((size_t)bh*Nn + n)*TOPKc + lane];
    __syncwarp();

    const float scale = 0.125f;
    const int NSEL = TOPKc * BLKc;   // 56
    const float NEGINF = -__int_as_float(0x7f800000);
    const float4* sq4 = reinterpret_cast<const float4*>(sq[warp]);

    float l0, l1;
    {
        int s = lane;
        int tok = sblk[warp][s >> 3] * BLKc + (s & 7);
        const float4* kr4 = reinterpret_cast<const float4*>(
            g_k + ((size_t)bh*Nn + tok) * Dd);
        float a = 0.f;
#pragma unroll
        for (int t = 0; t < 16; t++) {
            float4 qv = sq4[t];
            float4 kv = __ldg(kr4 + t);
            a += qv.x*kv.x + qv.y*kv.y + qv.z*kv.z + qv.w*kv.w;
        }
        l0 = a * scale;
    }
    {
        int s = lane + 32;
        if (s < NSEL) {
            int tok = sblk[warp][s >> 3] * BLKc + (s & 7);
            const float4* kr4 = reinterpret_cast<const float4*>(
                g_k + ((size_t)bh*Nn + tok) * Dd);
            float a = 0.f;
#pragma unroll
            for (int t = 0; t < 16; t++) {
                float4 qv = sq4[t];
                float4 kv = __ldg(kr4 + t);
                a += qv.x*kv.x + qv.y*kv.y + qv.z*kv.z + qv.w*kv.w;
            }
            l1 = a * scale;
        } else l1 = NEGINF;
    }
    float mx = fmaxf(l0, l1);
#pragma unroll
    for (int o = 16; o; o >>= 1) mx = fmaxf(mx, __shfl_xor_sync(~0u, mx, o));
    float e0 = __expf(l0 - mx);
    float e1 = (lane + 32 < NSEL) ? __expf(l1 - mx) : 0.f;
    float se = e0 + e1;
#pragma unroll
    for (int o = 16; o; o >>= 1) se += __shfl_xor_sync(~0u, se, o);
    float inv = 1.f / se;
    sp[warp][lane]      = e0 * inv;
    sp[warp][lane + 32] = e1 * inv;
    __syncwarp();

    int d0 = lane, d1 = lane + 32;
    float a0 = 0.f, a1 = 0.f;
#pragma unroll
    for (int s = 0; s < NSEL; s++) {
        int tok = sblk[warp][s >> 3] * BLKc + (s & 7);
        const float* vr = g_v + ((size_t)bh*Nn + tok) * Dd;
        float p = sp[warp][s];
        a0 += p * vr[d0];
        a1 += p * vr[d1];
    }

    const float* zr = g_z + (size_t)bh * Dd;
    float t = spq[warp][d0]*zr[d0] + spq[warp][d1]*zr[d1];
#pragma unroll
    for (int o = 16; o; o >>= 1) t += __shfl_xor_sync(~0u, t, o);
    float inv_den = 1.f / (t + 1e-6f);
    const float* kvm = g_kv + (size_t)bh * Dd * Dd;
    float n0a = 0.f, n1a = 0.f;
#pragma unroll
    for (int e = 0; e < 64; e++) {
        float pe = spq[warp][e];
        n0a += pe * kvm[e*Dd + d0];
        n1a += pe * kvm[e*Dd + d1];
    }
    size_t ob = ((size_t)(b*Nn + n)) * Cc + h*Dd;
    g_attn[ob + d0] = a0 + n0a * inv_den;
    g_attn[ob + d1] = a1 + n1a * inv_den;
}

// ---------------------------------------------------------------------------
extern "C" void kernel_launch(void* const* d_in, const int* in_sizes, int n_in,
                              void* d_out, int out_size)
{
    const float* x      = (const float*)d_in[0];
    const float* w_qkv  = (const float*)d_in[1];
    const float* b_qkv  = (const float*)d_in[2];
    const float* qw     = (const float*)d_in[3];
    const float* qb     = (const float*)d_in[4];
    const float* kw     = (const float*)d_in[5];
    const float* kb     = (const float*)d_in[6];
    const float* w_proj = (const float*)d_in[7];
    const float* b_proj = (const float*)d_in[8];
    float* out = (float*)d_out;

    void *p_qkv = nullptr, *p_attn = nullptr;
    cudaGetSymbolAddress(&p_qkv,  g_qkv);
    cudaGetSymbolAddress(&p_attn, g_attn);

    // 1) qkv = x @ w_qkv + b_qkv
    {
        dim3 grid(3*Cc/GBN, Bb*Nn/GBM);
        gemm_tf32_kernel<<<grid, 256>>>(x, w_qkv, b_qkv, (float*)p_qkv,
                                        Bb*Nn, 3*Cc, Cc);
    }
    // 2) layernorm + phi + split heads
    ln_phi_kernel<<<Bb*Nn, 512>>>(qw, qb, kw, kb);
    // 3) compressed keys
    kcmp_kernel<<<BHc*NBc, 64>>>();
    // 4) kv / z
    {
        dim3 grid(BHc, NCHUNK);
        kv_chunk_kernel<<<grid, 256>>>();
        int total = BHc*Dd*Dd + BHc*Dd;
        kv_reduce_kernel<<<(total + 255)/256, 256>>>();
    }
    // 5) router + topk
    router_topk_kernel<<<BHc*(Nn/64), 256>>>();
    // 6) sparse + linear attention
    attn_kernel<<<BHc*(Nn/8), 256>>>();
    // 7) out = attn @ w_proj + b_proj
    {
        dim3 grid(Cc/GBN, Bb*Nn/GBM);
        gemm_tf32_kernel<<<grid, 256>>>((const float*)p_attn, w_proj, b_proj,
                                        out, Bb*Nn, Cc, Cc);
    }
    (void)in_sizes; (void)n_in; (void)out_size;
}

// round 6
// speedup vs baseline: 1.0026x; 1.0011x over previous
#include <cuda_runtime.h>
#include <math.h>
#include <stdint.h>

// Problem constants
#define Bb   2
#define Nn   1024
#define Cc   1024
#define Hh   16
#define Dd   64
#define BLKc 8
#define NBc  128
#define TOPKc 7
#define BHc  (Bb*Hh)          // 32
#define NCHUNK 16             // kv accumulation chunks
#define CHLEN (Nn/NCHUNK)     // 64

// ---------------- scratch (device globals; no allocation) ----------------
__device__ __align__(16) float g_qkv [Bb*Nn*3*Cc];        // (B,N,3C)
__device__ __align__(16) float g_q   [BHc*Nn*Dd];
__device__ __align__(16) float g_k   [BHc*Nn*Dd];
__device__ __align__(16) float g_v   [BHc*Nn*Dd];
__device__ __align__(16) float g_pq  [BHc*Nn*Dd];         // phi_q
__device__ __align__(16) float g_pk  [BHc*Nn*Dd];         // phi_k
__device__ __align__(16) float g_kcmp[BHc*NBc*Dd];
__device__               int   g_topk[BHc*Nn*TOPKc];
__device__ __align__(16) float g_kvp [NCHUNK*BHc*Dd*Dd];  // partial kv
__device__ __align__(16) float g_zp  [NCHUNK*BHc*Dd];     // partial z
__device__ __align__(16) float g_kv  [BHc*Dd*Dd];
__device__ __align__(16) float g_z   [BHc*Dd];
__device__ __align__(16) float g_attn[Bb*Nn*Cc];          // (B,N,C) pre-proj

// =============== tf32 tensor-core GEMM (3xTF32 for fp32 accuracy) ========
#define GBM 128
#define GBN 64
#define GBK 16
#define ASTR 136
#define BSTR 72

__device__ __forceinline__ uint32_t f2tf32(float x) {
    uint32_t r;
    asm("cvt.rna.tf32.f32 %0, %1;" : "=r"(r) : "f"(x));
    return r;
}

__device__ __forceinline__ void mma_tf32(float* d, const uint32_t* a, const uint32_t* b) {
    asm volatile(
        "mma.sync.aligned.m16n8k8.row.col.f32.tf32.tf32.f32 "
        "{%0,%1,%2,%3}, {%4,%5,%6,%7}, {%8,%9}, {%0,%1,%2,%3};"
        : "+f"(d[0]), "+f"(d[1]), "+f"(d[2]), "+f"(d[3])
        : "r"(a[0]), "r"(a[1]), "r"(a[2]), "r"(a[3]), "r"(b[0]), "r"(b[1]));
}

__global__ __launch_bounds__(256) void gemm_tf32_kernel(
    const float* __restrict__ A, const float* __restrict__ B,
    const float* __restrict__ bias, float* __restrict__ C,
    int M, int N, int K)
{
    __shared__ float As[2][GBK*ASTR];
    __shared__ float Bs[2][GBK*BSTR];
    const int tid  = threadIdx.x;
    const int lane = tid & 31;
    const int warp = tid >> 5;
    const int warpM = warp & 3;
    const int warpN = warp >> 2;
    const int g  = lane >> 2;
    const int tq = lane & 3;
    const int bm = blockIdx.y * GBM;
    const int bn = blockIdx.x * GBN;

    const int aR  = tid >> 1;
    const int aKq = (tid & 1) * 2;
    const int bK  = tid >> 4;
    const int bN4 = (tid & 15) * 4;

    float acc[2][4][4];
#pragma unroll
    for (int mf = 0; mf < 2; mf++)
#pragma unroll
        for (int nf = 0; nf < 4; nf++)
#pragma unroll
            for (int r = 0; r < 4; r++) acc[mf][nf][r] = 0.f;

    const int nIter = K / GBK;

    {
        float4 a0 = *reinterpret_cast<const float4*>(A + (size_t)(bm + aR) * K + (aKq + 0) * 4);
        float4 a1 = *reinterpret_cast<const float4*>(A + (size_t)(bm + aR) * K + (aKq + 1) * 4);
        float4 bv = *reinterpret_cast<const float4*>(B + (size_t)bK * N + bn + bN4);
        As[0][(aKq*4 + 0)*ASTR + aR] = a0.x;
        As[0][(aKq*4 + 1)*ASTR + aR] = a0.y;
        As[0][(aKq*4 + 2)*ASTR + aR] = a0.z;
        As[0][(aKq*4 + 3)*ASTR + aR] = a0.w;
        As[0][(aKq*4 + 4)*ASTR + aR] = a1.x;
        As[0][(aKq*4 + 5)*ASTR + aR] = a1.y;
        As[0][(aKq*4 + 6)*ASTR + aR] = a1.z;
        As[0][(aKq*4 + 7)*ASTR + aR] = a1.w;
        *reinterpret_cast<float4*>(&Bs[0][bK*BSTR + bN4]) = bv;
    }
    __syncthreads();

    for (int it = 0; it < nIter; it++) {
        const int buf = it & 1;
        float4 na0, na1, nb;
        const bool more = (it + 1 < nIter);
        if (more) {
            int k0 = (it + 1) * GBK;
            na0 = *reinterpret_cast<const float4*>(A + (size_t)(bm + aR) * K + k0 + (aKq + 0) * 4);
            na1 = *reinterpret_cast<const float4*>(A + (size_t)(bm + aR) * K + k0 + (aKq + 1) * 4);
            nb  = *reinterpret_cast<const float4*>(B + (size_t)(k0 + bK) * N + bn + bN4);
        }

        const float* as = As[buf];
        const float* bs = Bs[buf];
#pragma unroll
        for (int ks = 0; ks < 2; ks++) {
            const int kb = ks * 8;
            uint32_t ahi[2][4], alo[2][4];
#pragma unroll
            for (int mf = 0; mf < 2; mf++) {
                const int m = warpM * 32 + mf * 16 + g;
                const float* p = as + (kb + tq) * ASTR + m;
                float v0 = p[0];
                float v1 = p[8];
                float v2 = p[4*ASTR];
                float v3 = p[4*ASTR + 8];
                ahi[mf][0] = f2tf32(v0); alo[mf][0] = f2tf32(v0 - __uint_as_float(ahi[mf][0]));
                ahi[mf][1] = f2tf32(v1); alo[mf][1] = f2tf32(v1 - __uint_as_float(ahi[mf][1]));
                ahi[mf][2] = f2tf32(v2); alo[mf][2] = f2tf32(v2 - __uint_as_float(ahi[mf][2]));
                ahi[mf][3] = f2tf32(v3); alo[mf][3] = f2tf32(v3 - __uint_as_float(ahi[mf][3]));
            }
            uint32_t bhi[4][2], blo[4][2];
#pragma unroll
            for (int nf = 0; nf < 4; nf++) {
                const int n = warpN * 32 + nf * 8 + g;
                const float* p = bs + (kb + tq) * BSTR + n;
                float v0 = p[0];
                float v1 = p[4*BSTR];
                bhi[nf][0] = f2tf32(v0); blo[nf][0] = f2tf32(v0 - __uint_as_float(bhi[nf][0]));
                bhi[nf][1] = f2tf32(v1); blo[nf][1] = f2tf32(v1 - __uint_as_float(bhi[nf][1]));
            }
#pragma unroll
            for (int mf = 0; mf < 2; mf++)
#pragma unroll
                for (int nf = 0; nf < 4; nf++) mma_tf32(acc[mf][nf], ahi[mf], bhi[nf]);
#pragma unroll
            for (int mf = 0; mf < 2; mf++)
#pragma unroll
                for (int nf = 0; nf < 4; nf++) mma_tf32(acc[mf][nf], alo[mf], bhi[nf]);
#pragma unroll
            for (int mf = 0; mf < 2; mf++)
#pragma unroll
                for (int nf = 0; nf < 4; nf++) mma_tf32(acc[mf][nf], ahi[mf], blo[nf]);
        }

        if (more) {
            const int nbuf = buf ^ 1;
            As[nbuf][(aKq*4 + 0)*ASTR + aR] = na0.x;
            As[nbuf][(aKq*4 + 1)*ASTR + aR] = na0.y;
            As[nbuf][(aKq*4 + 2)*ASTR + aR] = na0.z;
            As[nbuf][(aKq*4 + 3)*ASTR + aR] = na0.w;
            As[nbuf][(aKq*4 + 4)*ASTR + aR] = na1.x;
            As[nbuf][(aKq*4 + 5)*ASTR + aR] = na1.y;
            As[nbuf][(aKq*4 + 6)*ASTR + aR] = na1.z;
            As[nbuf][(aKq*4 + 7)*ASTR + aR] = na1.w;
            *reinterpret_cast<float4*>(&Bs[nbuf][bK*BSTR + bN4]) = nb;
        }
        __syncthreads();
    }

#pragma unroll
    for (int mf = 0; mf < 2; mf++) {
#pragma unroll
        for (int nf = 0; nf < 4; nf++) {
            const int r0 = bm + warpM * 32 + mf * 16 + g;
            const int c0 = bn + warpN * 32 + nf * 8 + tq * 2;
            float2 bv = *reinterpret_cast<const float2*>(bias + c0);
            float2 o0 = make_float2(acc[mf][nf][0] + bv.x, acc[mf][nf][1] + bv.y);
            float2 o1 = make_float2(acc[mf][nf][2] + bv.x, acc[mf][nf][3] + bv.y);
            *reinterpret_cast<float2*>(C + (size_t)r0 * N + c0)       = o0;
            *reinterpret_cast<float2*>(C + (size_t)(r0 + 8) * N + c0) = o1;
        }
    }
}

// ------------- LayerNorm(q,k) + phi softmax + v copy, per (b,n) ----------
__global__ __launch_bounds__(512) void ln_phi_kernel(
    const float* __restrict__ qw, const float* __restrict__ qb,
    const float* __restrict__ kw, const float* __restrict__ kb)
{
    int bn = blockIdx.x;
    int b = bn / Nn, n = bn % Nn;
    int h = threadIdx.x >> 5;
    int lane = threadIdx.x & 31;
    const float* row = g_qkv + (size_t)bn * (3*Cc);
    int d0 = lane, d1 = lane + 32;
    size_t obase = ((size_t)(b*Hh + h) * Nn + n) * Dd;

    // ---- q ----
    {
        float v0 = row[h*Dd + d0], v1 = row[h*Dd + d1];
        float s = v0 + v1;
#pragma unroll
        for (int o = 16; o; o >>= 1) s += __shfl_xor_sync(~0u, s, o);
        float m = s * (1.f/64.f);
        float a0 = v0 - m, a1 = v1 - m;
        float vs = a0*a0 + a1*a1;
#pragma unroll
        for (int o = 16; o; o >>= 1) vs += __shfl_xor_sync(~0u, vs, o);
        float r = rsqrtf(vs * (1.f/64.f) + 1e-6f);
        float y0 = a0*r*qw[d0] + qb[d0];
        float y1 = a1*r*qw[d1] + qb[d1];
        g_q[obase + d0] = y0; g_q[obase + d1] = y1;
        float mx = fmaxf(y0, y1);
#pragma unroll
        for (int o = 16; o; o >>= 1) mx = fmaxf(mx, __shfl_xor_sync(~0u, mx, o));
        float e0 = __expf(y0 - mx), e1 = __expf(y1 - mx);
        float se = e0 + e1;
#pragma unroll
        for (int o = 16; o; o >>= 1) se += __shfl_xor_sync(~0u, se, o);
        float inv = 1.f / se;
        g_pq[obase + d0] = e0*inv; g_pq[obase + d1] = e1*inv;
    }
    // ---- k ----
    {
        float v0 = row[Cc + h*Dd + d0], v1 = row[Cc + h*Dd + d1];
        float s = v0 + v1;
#pragma unroll
        for (int o = 16; o; o >>= 1) s += __shfl_xor_sync(~0u, s, o);
        float m = s * (1.f/64.f);
        float a0 = v0 - m, a1 = v1 - m;
        float vs = a0*a0 + a1*a1;
#pragma unroll
        for (int o = 16; o; o >>= 1) vs += __shfl_xor_sync(~0u, vs, o);
        float r = rsqrtf(vs * (1.f/64.f) + 1e-6f);
        float y0 = a0*r*kw[d0] + kb[d0];
        float y1 = a1*r*kw[d1] + kb[d1];
        g_k[obase + d0] = y0; g_k[obase + d1] = y1;
        float mx = fmaxf(y0, y1);
#pragma unroll
        for (int o = 16; o; o >>= 1) mx = fmaxf(mx, __shfl_xor_sync(~0u, mx, o));
        float e0 = __expf(y0 - mx), e1 = __expf(y1 - mx);
        float se = e0 + e1;
#pragma unroll
        for (int o = 16; o; o >>= 1) se += __shfl_xor_sync(~0u, se, o);
        float inv = 1.f / se;
        g_pk[obase + d0] = e0*inv; g_pk[obase + d1] = e1*inv;
    }
    // ---- v copy ----
    g_v[obase + d0] = row[2*Cc + h*Dd + d0];
    g_v[obase + d1] = row[2*Cc + h*Dd + d1];
}

// ------------- compressed keys: mean pool over BLK=8 ---------------------
__global__ __launch_bounds__(64) void kcmp_kernel()
{
    int bhm = blockIdx.x;            // B*H*NB
    int d = threadIdx.x;
    int bh = bhm / NBc, m = bhm % NBc;
    const float* kr = g_k + ((size_t)bh*Nn + m*BLKc) * Dd;
    float s = 0.f;
#pragma unroll
    for (int t = 0; t < BLKc; t++) s += kr[t*Dd + d];
    g_kcmp[(size_t)bhm*Dd + d] = s * (1.f/BLKc);
}

// ------------- kv/z partials (deterministic, no atomics) -----------------
__global__ __launch_bounds__(256) void kv_chunk_kernel()
{
    int bh = blockIdx.x;
    int ch = blockIdx.y;
    int tid = threadIdx.x;
    int e = tid & 63;
    int dg = tid >> 6;               // 0..3
    __shared__ float sh[4][128];
    float acc[16];
#pragma unroll
    for (int j = 0; j < 16; j++) acc[j] = 0.f;
    float zacc = 0.f;
    size_t base = (size_t)bh * Nn * Dd;
    const int lr = tid >> 6;
    const int lc = (tid & 63) * 2;
    for (int i0 = 0; i0 < CHLEN; i0 += 4) {
        __syncthreads();
        {
            int n = ch * CHLEN + i0 + lr;
            float2 val;
            if (lc < 64)
                val = *reinterpret_cast<const float2*>(g_pk + base + (size_t)n*Dd + lc);
            else
                val = *reinterpret_cast<const float2*>(g_v + base + (size_t)n*Dd + (lc - 64));
            sh[lr][lc]   = val.x;
            sh[lr][lc+1] = val.y;
        }
        __syncthreads();
#pragma unroll
        for (int r = 0; r < 4; r++) {
            float ve = sh[r][64 + e];
#pragma unroll
            for (int j = 0; j < 16; j++) acc[j] += sh[r][dg*16 + j] * ve;
            if (tid < 64) zacc += sh[r][tid];
        }
    }
    float* out = g_kvp + ((size_t)ch * BHc + bh) * (Dd*Dd);
#pragma unroll
    for (int j = 0; j < 16; j++) out[(dg*16 + j)*Dd + e] = acc[j];
    if (tid < 64) g_zp[((size_t)ch * BHc + bh) * Dd + tid] = zacc;
}

__global__ __launch_bounds__(256) void kv_reduce_kernel()
{
    int idx = blockIdx.x * 256 + threadIdx.x;
    const int KVN = BHc*Dd*Dd;
    const int ZN  = BHc*Dd;
    if (idx < KVN) {
        float s = 0.f;
#pragma unroll
        for (int c = 0; c < NCHUNK; c++) s += g_kvp[(size_t)c*KVN + idx];
        g_kv[idx] = s;
    } else if (idx < KVN + ZN) {
        int z = idx - KVN;
        float s = 0.f;
#pragma unroll
        for (int c = 0; c < NCHUNK; c++) s += g_zp[(size_t)c*ZN + z];
        g_z[z] = s;
    }
}

// ------------- router + top-7 v2 : smem-transposed kcmp ------------------
// grid = BH * (N/64), 256 threads = 8 warps; each warp does 8 queries.
#define KCSTR 132   // row stride (floats), 16B multiple, conflict-free LDS.128
__global__ __launch_bounds__(256) void router_topk_kernel()
{
    __shared__ float kct[Dd * KCSTR];   // [d][blk], 33.8KB
    int bh = blockIdx.x >> 4;           // Nn/64 = 16 query tiles
    int n0 = (blockIdx.x & 15) * 64;
    int tid = threadIdx.x;
    int warp = tid >> 5, lane = tid & 31;

    // transpose-load kcmp (coalesced global reads)
    const float* kc = g_kcmp + (size_t)bh * NBc * Dd;
#pragma unroll
    for (int i = 0; i < 32; i++) {
        int idx = tid + i * 256;        // 0..8191
        int blk = idx >> 6, d = idx & 63;
        kct[d * KCSTR + blk] = kc[idx];
    }
    __syncthreads();

    const float scale = 0.125f;
    const float NEGINF = -__int_as_float(0x7f800000);

    for (int qi = 0; qi < 8; qi++) {
        int n = n0 + warp * 8 + qi;
        const float* qrow = g_q + ((size_t)bh*Nn + n) * Dd;
        float q0 = qrow[lane], q1 = qrow[lane + 32];
        float s0 = 0.f, s1 = 0.f, s2 = 0.f, s3 = 0.f;
#pragma unroll
        for (int d = 0; d < 64; d++) {
            float qd = (d < 32) ? __shfl_sync(~0u, q0, d)
                                : __shfl_sync(~0u, q1, d - 32);
            float4 kv4 = *reinterpret_cast<const float4*>(&kct[d * KCSTR + lane * 4]);
            s0 += qd * kv4.x; s1 += qd * kv4.y;
            s2 += qd * kv4.z; s3 += qd * kv4.w;
        }
        s0 *= scale; s1 *= scale; s2 *= scale; s3 *= scale;

        int qidx = bh * Nn + n;
#pragma unroll
        for (int r = 0; r < TOPKc; r++) {
            float bv = s0; int bj = 0;
            if (s1 > bv) { bv = s1; bj = 1; }
            if (s2 > bv) { bv = s2; bj = 2; }
            if (s3 > bv) { bv = s3; bj = 3; }
            int bm = lane * 4 + bj;
#pragma unroll
            for (int o = 16; o; o >>= 1) {
                float ov = __shfl_xor_sync(~0u, bv, o);
                int   om = __shfl_xor_sync(~0u, bm, o);
                if (ov > bv || (ov == bv && om < bm)) { bv = ov; bm = om; }
            }
            if ((bm >> 2) == lane) {
                int j = bm & 3;
                if      (j == 0) s0 = NEGINF;
                else if (j == 1) s1 = NEGINF;
                else if (j == 2) s2 = NEGINF;
                else             s3 = NEGINF;
            }
            if (lane == 0) g_topk[(size_t)qidx*TOPKc + r] = bm;
        }
    }
}

// ------------- fused sparse softmax attention + linear branch ------------
__global__ __launch_bounds__(256) void attn_kernel()
{
    int bh = blockIdx.x / (Nn/8);
    int b = bh / Hh, h = bh % Hh;
    int n0 = (blockIdx.x % (Nn/8)) * 8;
    int warp = threadIdx.x >> 5;
    int lane = threadIdx.x & 31;
    int n = n0 + warp;
    __shared__ float sq [8][64];
    __shared__ float spq[8][64];
    __shared__ float sp [8][64];
    __shared__ int   sblk[8][8];

    size_t qb = ((size_t)bh*Nn + n) * Dd;
    {
        float2 a = *reinterpret_cast<const float2*>(g_q  + qb + lane*2);
        float2 c = *reinterpret_cast<const float2*>(g_pq + qb + lane*2);
        sq [warp][lane*2] = a.x; sq [warp][lane*2+1] = a.y;
        spq[warp][lane*2] = c.x; spq[warp][lane*2+1] = c.y;
    }
    if (lane < TOPKc) sblk[warp][lane] = g_topk[((size_t)bh*Nn + n)*TOPKc + lane];
    __syncwarp();

    const float scale = 0.125f;
    const int NSEL = TOPKc * BLKc;   // 56
    const float NEGINF = -__int_as_float(0x7f800000);
    const float4* sq4 = reinterpret_cast<const float4*>(sq[warp]);

    float l0, l1;
    {
        int s = lane;
        int tok = sblk[warp][s >> 3] * BLKc + (s & 7);
        const float4* kr4 = reinterpret_cast<const float4*>(
            g_k + ((size_t)bh*Nn + tok) * Dd);
        float a = 0.f;
#pragma unroll
        for (int t = 0; t < 16; t++) {
            float4 qv = sq4[t];
            float4 kv = __ldg(kr4 + t);
            a += qv.x*kv.x + qv.y*kv.y + qv.z*kv.z + qv.w*kv.w;
        }
        l0 = a * scale;
    }
    {
        int s = lane + 32;
        if (s < NSEL) {
            int tok = sblk[warp][s >> 3] * BLKc + (s & 7);
            const float4* kr4 = reinterpret_cast<const float4*>(
                g_k + ((size_t)bh*Nn + tok) * Dd);
            float a = 0.f;
#pragma unroll
            for (int t = 0; t < 16; t++) {
                float4 qv = sq4[t];
                float4 kv = __ldg(kr4 + t);
                a += qv.x*kv.x + qv.y*kv.y + qv.z*kv.z + qv.w*kv.w;
            }
            l1 = a * scale;
        } else l1 = NEGINF;
    }
    float mx = fmaxf(l0, l1);
#pragma unroll
    for (int o = 16; o; o >>= 1) mx = fmaxf(mx, __shfl_xor_sync(~0u, mx, o));
    float e0 = __expf(l0 - mx);
    float e1 = (lane + 32 < NSEL) ? __expf(l1 - mx) : 0.f;
    float se = e0 + e1;
#pragma unroll
    for (int o = 16; o; o >>= 1) se += __shfl_xor_sync(~0u, se, o);
    float inv = 1.f / se;
    sp[warp][lane]      = e0 * inv;
    sp[warp][lane + 32] = e1 * inv;
    __syncwarp();

    int d0 = lane, d1 = lane + 32;
    float a0 = 0.f, a1 = 0.f;
#pragma unroll
    for (int s = 0; s < NSEL; s++) {
        int tok = sblk[warp][s >> 3] * BLKc + (s & 7);
        const float* vr = g_v + ((size_t)bh*Nn + tok) * Dd;
        float p = sp[warp][s];
        a0 += p * vr[d0];
        a1 += p * vr[d1];
    }

    const float* zr = g_z + (size_t)bh * Dd;
    float t = spq[warp][d0]*zr[d0] + spq[warp][d1]*zr[d1];
#pragma unroll
    for (int o = 16; o; o >>= 1) t += __shfl_xor_sync(~0u, t, o);
    float inv_den = 1.f / (t + 1e-6f);
    const float* kvm = g_kv + (size_t)bh * Dd * Dd;
    float n0a = 0.f, n1a = 0.f;
#pragma unroll
    for (int e = 0; e < 64; e++) {
        float pe = spq[warp][e];
        n0a += pe * kvm[e*Dd + d0];
        n1a += pe * kvm[e*Dd + d1];
    }
    size_t ob = ((size_t)(b*Nn + n)) * Cc + h*Dd;
    g_attn[ob + d0] = a0 + n0a * inv_den;
    g_attn[ob + d1] = a1 + n1a * inv_den;
}

// ---------------------------------------------------------------------------
extern "C" void kernel_launch(void* const* d_in, const int* in_sizes, int n_in,
                              void* d_out, int out_size)
{
    const float* x      = (const float*)d_in[0];
    const float* w_qkv  = (const float*)d_in[1];
    const float* b_qkv  = (const float*)d_in[2];
    const float* qw     = (const float*)d_in[3];
    const float* qb     = (const float*)d_in[4];
    const float* kw     = (const float*)d_in[5];
    const float* kb     = (const float*)d_in[6];
    const float* w_proj = (const float*)d_in[7];
    const float* b_proj = (const float*)d_in[8];
    float* out = (float*)d_out;

    void *p_qkv = nullptr, *p_attn = nullptr;
    cudaGetSymbolAddress(&p_qkv,  g_qkv);
    cudaGetSymbolAddress(&p_attn, g_attn);

    // 1) qkv = x @ w_qkv + b_qkv
    {
        dim3 grid(3*Cc/GBN, Bb*Nn/GBM);
        gemm_tf32_kernel<<<grid, 256>>>(x, w_qkv, b_qkv, (float*)p_qkv,
                                        Bb*Nn, 3*Cc, Cc);
    }
    // 2) layernorm + phi + split heads
    ln_phi_kernel<<<Bb*Nn, 512>>>(qw, qb, kw, kb);
    // 3) compressed keys
    kcmp_kernel<<<BHc*NBc, 64>>>();
    // 4) kv / z
    {
        dim3 grid(BHc, NCHUNK);
        kv_chunk_kernel<<<grid, 256>>>();
        int total = BHc*Dd*Dd + BHc*Dd;
        kv_reduce_kernel<<<(total + 255)/256, 256>>>();
    }
    // 5) router + topk
    router_topk_kernel<<<BHc*(Nn/64), 256>>>();
    // 6) sparse + linear attention
    attn_kernel<<<BHc*(Nn/8), 256>>>();
    // 7) out = attn @ w_proj + b_proj
    {
        dim3 grid(Cc/GBN, Bb*Nn/GBM);
        gemm_tf32_kernel<<<grid, 256>>>((const float*)p_attn, w_proj, b_proj,
                                        out, Bb*Nn, Cc, Cc);
    }
    (void)in_sizes; (void)n_in; (void)out_size;
}

// round 7
// speedup vs baseline: 1.2225x; 1.2194x over previous
#include <cuda_runtime.h>
#include <math.h>
#include <stdint.h>

// Problem constants
#define Bb   2
#define Nn   1024
#define Cc   1024
#define Hh   16
#define Dd   64
#define BLKc 8
#define NBc  128
#define TOPKc 7
#define BHc  (Bb*Hh)          // 32
#define NCHUNK 16
#define CHLEN (Nn/NCHUNK)     // 64
#define K2c  (Cc/2)           // 512 bf16-pair columns

// ---------------- scratch (device globals; no allocation) ----------------
__device__ __align__(16) float g_qkv [Bb*Nn*3*Cc];
__device__ __align__(16) float g_q   [BHc*Nn*Dd];
__device__ __align__(16) float g_k   [BHc*Nn*Dd];
__device__ __align__(16) float g_v   [BHc*Nn*Dd];
__device__ __align__(16) float g_pq  [BHc*Nn*Dd];
__device__ __align__(16) float g_pk  [BHc*Nn*Dd];
__device__ __align__(16) float g_kcmp[BHc*NBc*Dd];
__device__               int   g_topk[BHc*Nn*TOPKc];
__device__ __align__(16) float g_kvp [NCHUNK*BHc*Dd*Dd];
__device__ __align__(16) float g_zp  [NCHUNK*BHc*Dd];
__device__ __align__(16) float g_kv  [BHc*Dd*Dd];
__device__ __align__(16) float g_z   [BHc*Dd];
__device__ __align__(16) float g_attn[Bb*Nn*Cc];
// bf16 hi/lo packed pair operands
__device__ __align__(16) uint32_t g_xh [Bb*Nn*K2c];   // x split  [M][K2]
__device__ __align__(16) uint32_t g_xl [Bb*Nn*K2c];
__device__ __align__(16) uint32_t g_ah [Bb*Nn*K2c];   // attn split
__device__ __align__(16) uint32_t g_al [Bb*Nn*K2c];
__device__ __align__(16) uint32_t g_wvh[K2c*Cc];      // w_qkv v-cols [K2][N]
__device__ __align__(16) uint32_t g_wvl[K2c*Cc];
__device__ __align__(16) uint32_t g_wph[K2c*Cc];      // w_proj [K2][N]
__device__ __align__(16) uint32_t g_wpl[K2c*Cc];

// ---------------- bf16 split helper --------------------------------------
__device__ __forceinline__ void bf16_split2(float x0, float x1,
                                            uint32_t& ph, uint32_t& pl) {
    uint32_t h;
    asm("cvt.rn.bf16x2.f32 %0, %1, %2;" : "=r"(h) : "f"(x1), "f"(x0)); // hi=x1 lo=x0
    float h0 = __uint_as_float(h << 16);
    float h1 = __uint_as_float(h & 0xffff0000u);
    float r0 = x0 - h0, r1 = x1 - h1;
    uint32_t l;
    asm("cvt.rn.bf16x2.f32 %0, %1, %2;" : "=r"(l) : "f"(r1), "f"(r0));
    ph = h; pl = l;
}

// pairs along contiguous dim (A matrices, row-major MxK)
__global__ __launch_bounds__(256) void split_a_kernel(
    const float* __restrict__ in, uint32_t* __restrict__ oh,
    uint32_t* __restrict__ ol, int npairs)
{
    int i = blockIdx.x * 256 + threadIdx.x;
    if (i >= npairs) return;
    float2 v = reinterpret_cast<const float2*>(in)[i];
    uint32_t h, l;
    bf16_split2(v.x, v.y, h, l);
    oh[i] = h; ol[i] = l;
}

// pairs across rows (B matrices KxN row-major -> [K2][N] packed)
__global__ __launch_bounds__(256) void split_b_kernel(
    const float* __restrict__ in, uint32_t* __restrict__ oh,
    uint32_t* __restrict__ ol, int ldb)
{
    int i = blockIdx.x * 256 + threadIdx.x;   // over K2c*Cc
    int k2 = i >> 10, n = i & 1023;           // N = 1024
    float x0 = in[(size_t)(2*k2)   * ldb + n];
    float x1 = in[(size_t)(2*k2+1) * ldb + n];
    uint32_t h, l;
    bf16_split2(x0, x1, h, l);
    oh[i] = h; ol[i] = l;
}

// =============== tf32 tensor-core GEMM (3xTF32) ===========================
#define GBM 128
#define GBN 64
#define GBK 16
#define ASTR 136
#define BSTR 72

__device__ __forceinline__ uint32_t f2tf32(float x) {
    uint32_t r;
    asm("cvt.rna.tf32.f32 %0, %1;" : "=r"(r) : "f"(x));
    return r;
}

__device__ __forceinline__ void mma_tf32(float* d, const uint32_t* a, const uint32_t* b) {
    asm volatile(
        "mma.sync.aligned.m16n8k8.row.col.f32.tf32.tf32.f32 "
        "{%0,%1,%2,%3}, {%4,%5,%6,%7}, {%8,%9}, {%0,%1,%2,%3};"
        : "+f"(d[0]), "+f"(d[1]), "+f"(d[2]), "+f"(d[3])
        : "r"(a[0]), "r"(a[1]), "r"(a[2]), "r"(a[3]), "r"(b[0]), "r"(b[1]));
}

__global__ __launch_bounds__(256) void gemm_tf32_kernel(
    const float* __restrict__ A, const float* __restrict__ B,
    const float* __restrict__ bias, float* __restrict__ C,
    int M, int K, int ldb, int ldc)
{
    __shared__ float As[2][GBK*ASTR];
    __shared__ float Bs[2][GBK*BSTR];
    const int tid  = threadIdx.x;
    const int lane = tid & 31;
    const int warp = tid >> 5;
    const int warpM = warp & 3;
    const int warpN = warp >> 2;
    const int g  = lane >> 2;
    const int tq = lane & 3;
    const int bm = blockIdx.y * GBM;
    const int bn = blockIdx.x * GBN;

    const int aR  = tid >> 1;
    const int aKq = (tid & 1) * 2;
    const int bK  = tid >> 4;
    const int bN4 = (tid & 15) * 4;

    float acc[2][4][4];
#pragma unroll
    for (int mf = 0; mf < 2; mf++)
#pragma unroll
        for (int nf = 0; nf < 4; nf++)
#pragma unroll
            for (int r = 0; r < 4; r++) acc[mf][nf][r] = 0.f;

    const int nIter = K / GBK;

    {
        float4 a0 = *reinterpret_cast<const float4*>(A + (size_t)(bm + aR) * K + (aKq + 0) * 4);
        float4 a1 = *reinterpret_cast<const float4*>(A + (size_t)(bm + aR) * K + (aKq + 1) * 4);
        float4 bv = *reinterpret_cast<const float4*>(B + (size_t)bK * ldb + bn + bN4);
        As[0][(aKq*4 + 0)*ASTR + aR] = a0.x;
        As[0][(aKq*4 + 1)*ASTR + aR] = a0.y;
        As[0][(aKq*4 + 2)*ASTR + aR] = a0.z;
        As[0][(aKq*4 + 3)*ASTR + aR] = a0.w;
        As[0][(aKq*4 + 4)*ASTR + aR] = a1.x;
        As[0][(aKq*4 + 5)*ASTR + aR] = a1.y;
        As[0][(aKq*4 + 6)*ASTR + aR] = a1.z;
        As[0][(aKq*4 + 7)*ASTR + aR] = a1.w;
        *reinterpret_cast<float4*>(&Bs[0][bK*BSTR + bN4]) = bv;
    }
    __syncthreads();

    for (int it = 0; it < nIter; it++) {
        const int buf = it & 1;
        float4 na0, na1, nb;
        const bool more = (it + 1 < nIter);
        if (more) {
            int k0 = (it + 1) * GBK;
            na0 = *reinterpret_cast<const float4*>(A + (size_t)(bm + aR) * K + k0 + (aKq + 0) * 4);
            na1 = *reinterpret_cast<const float4*>(A + (size_t)(bm + aR) * K + k0 + (aKq + 1) * 4);
            nb  = *reinterpret_cast<const float4*>(B + (size_t)(k0 + bK) * ldb + bn + bN4);
        }

        const float* as = As[buf];
        const float* bs = Bs[buf];
#pragma unroll
        for (int ks = 0; ks < 2; ks++) {
            const int kb = ks * 8;
            uint32_t ahi[2][4], alo[2][4];
#pragma unroll
            for (int mf = 0; mf < 2; mf++) {
                const int m = warpM * 32 + mf * 16 + g;
                const float* p = as + (kb + tq) * ASTR + m;
                float v0 = p[0];
                float v1 = p[8];
                float v2 = p[4*ASTR];
                float v3 = p[4*ASTR + 8];
                ahi[mf][0] = f2tf32(v0); alo[mf][0] = f2tf32(v0 - __uint_as_float(ahi[mf][0]));
                ahi[mf][1] = f2tf32(v1); alo[mf][1] = f2tf32(v1 - __uint_as_float(ahi[mf][1]));
                ahi[mf][2] = f2tf32(v2); alo[mf][2] = f2tf32(v2 - __uint_as_float(ahi[mf][2]));
                ahi[mf][3] = f2tf32(v3); alo[mf][3] = f2tf32(v3 - __uint_as_float(ahi[mf][3]));
            }
            uint32_t bhi[4][2], blo[4][2];
#pragma unroll
            for (int nf = 0; nf < 4; nf++) {
                const int n = warpN * 32 + nf * 8 + g;
                const float* p = bs + (kb + tq) * BSTR + n;
                float v0 = p[0];
                float v1 = p[4*BSTR];
                bhi[nf][0] = f2tf32(v0); blo[nf][0] = f2tf32(v0 - __uint_as_float(bhi[nf][0]));
                bhi[nf][1] = f2tf32(v1); blo[nf][1] = f2tf32(v1 - __uint_as_float(bhi[nf][1]));
            }
#pragma unroll
            for (int mf = 0; mf < 2; mf++)
#pragma unroll
                for (int nf = 0; nf < 4; nf++) mma_tf32(acc[mf][nf], ahi[mf], bhi[nf]);
#pragma unroll
            for (int mf = 0; mf < 2; mf++)
#pragma unroll
                for (int nf = 0; nf < 4; nf++) mma_tf32(acc[mf][nf], alo[mf], bhi[nf]);
#pragma unroll
            for (int mf = 0; mf < 2; mf++)
#pragma unroll
                for (int nf = 0; nf < 4; nf++) mma_tf32(acc[mf][nf], ahi[mf], blo[nf]);
        }

        if (more) {
            const int nbuf = buf ^ 1;
            As[nbuf][(aKq*4 + 0)*ASTR + aR] = na0.x;
            As[nbuf][(aKq*4 + 1)*ASTR + aR] = na0.y;
            As[nbuf][(aKq*4 + 2)*ASTR + aR] = na0.z;
            As[nbuf][(aKq*4 + 3)*ASTR + aR] = na0.w;
            As[nbuf][(aKq*4 + 4)*ASTR + aR] = na1.x;
            As[nbuf][(aKq*4 + 5)*ASTR + aR] = na1.y;
            As[nbuf][(aKq*4 + 6)*ASTR + aR] = na1.z;
            As[nbuf][(aKq*4 + 7)*ASTR + aR] = na1.w;
            *reinterpret_cast<float4*>(&Bs[nbuf][bK*BSTR + bN4]) = nb;
        }
        __syncthreads();
    }

#pragma unroll
    for (int mf = 0; mf < 2; mf++) {
#pragma unroll
        for (int nf = 0; nf < 4; nf++) {
            const int r0 = bm + warpM * 32 + mf * 16 + g;
            const int c0 = bn + warpN * 32 + nf * 8 + tq * 2;
            float2 bv = *reinterpret_cast<const float2*>(bias + c0);
            float2 o0 = make_float2(acc[mf][nf][0] + bv.x, acc[mf][nf][1] + bv.y);
            float2 o1 = make_float2(acc[mf][nf][2] + bv.x, acc[mf][nf][3] + bv.y);
            *reinterpret_cast<float2*>(C + (size_t)r0 * ldc + c0)       = o0;
            *reinterpret_cast<float2*>(C + (size_t)(r0 + 8) * ldc + c0) = o1;
        }
    }
}

// =============== pre-split 3xbf16 GEMM (m16n8k16) =========================
// A: [M][K2] packed bf16x2 hi/lo, B: [K2][N] packed hi/lo, C fp32.
#define HASTR 136   // u32 stride for A smem rows
#define HBSTR 72

__device__ __forceinline__ void mma_bf16(float* d, const uint32_t* a, const uint32_t* b) {
    asm volatile(
        "mma.sync.aligned.m16n8k16.row.col.f32.bf16.bf16.f32 "
        "{%0,%1,%2,%3}, {%4,%5,%6,%7}, {%8,%9}, {%0,%1,%2,%3};"
        : "+f"(d[0]), "+f"(d[1]), "+f"(d[2]), "+f"(d[3])
        : "r"(a[0]), "r"(a[1]), "r"(a[2]), "r"(a[3]), "r"(b[0]), "r"(b[1]));
}

__global__ __launch_bounds__(256) void gemm_bf16_pre_kernel(
    const uint32_t* __restrict__ Ah, const uint32_t* __restrict__ Al,
    const uint32_t* __restrict__ Bh, const uint32_t* __restrict__ Bl,
    const float* __restrict__ bias, float* __restrict__ C,
    int K2, int N, int ldc)
{
    __shared__ uint32_t Ahs[2][8*HASTR];
    __shared__ uint32_t Als[2][8*HASTR];
    __shared__ uint32_t Bhs[2][8*HBSTR];
    __shared__ uint32_t Bls[2][8*HBSTR];
    const int tid  = threadIdx.x;
    const int lane = tid & 31;
    const int warp = tid >> 5;
    const int warpM = warp & 3;
    const int warpN = warp >> 2;
    const int g  = lane >> 2;
    const int tq = lane & 3;
    const int bm = blockIdx.y * GBM;
    const int bn = blockIdx.x * GBN;

    const int aR  = tid >> 1;            // 0..127
    const int aQ4 = (tid & 1) * 4;       // k2 quad base
    const int bK2 = tid >> 5;            // 0..7
    const int bC  = (lane) * 2;          // 0..62

    float acc[2][4][4];
#pragma unroll
    for (int mf = 0; mf < 2; mf++)
#pragma unroll
        for (int nf = 0; nf < 4; nf++)
#pragma unroll
            for (int r = 0; r < 4; r++) acc[mf][nf][r] = 0.f;

    const int nIter = K2 / 8;

    // prologue
    {
        uint4 ah = *reinterpret_cast<const uint4*>(Ah + (size_t)(bm + aR) * K2 + aQ4);
        uint4 al = *reinterpret_cast<const uint4*>(Al + (size_t)(bm + aR) * K2 + aQ4);
        uint2 bh = *reinterpret_cast<const uint2*>(Bh + (size_t)bK2 * N + bn + bC);
        uint2 bl = *reinterpret_cast<const uint2*>(Bl + (size_t)bK2 * N + bn + bC);
        Ahs[0][(aQ4+0)*HASTR + aR] = ah.x; Ahs[0][(aQ4+1)*HASTR + aR] = ah.y;
        Ahs[0][(aQ4+2)*HASTR + aR] = ah.z; Ahs[0][(aQ4+3)*HASTR + aR] = ah.w;
        Als[0][(aQ4+0)*HASTR + aR] = al.x; Als[0][(aQ4+1)*HASTR + aR] = al.y;
        Als[0][(aQ4+2)*HASTR + aR] = al.z; Als[0][(aQ4+3)*HASTR + aR] = al.w;
        *reinterpret_cast<uint2*>(&Bhs[0][bK2*HBSTR + bC]) = bh;
        *reinterpret_cast<uint2*>(&Bls[0][bK2*HBSTR + bC]) = bl;
    }
    __syncthreads();

    for (int it = 0; it < nIter; it++) {
        const int buf = it & 1;
        uint4 nah, nal; uint2 nbh, nbl;
        const bool more = (it + 1 < nIter);
        if (more) {
            int k2o = (it + 1) * 8;
            nah = *reinterpret_cast<const uint4*>(Ah + (size_t)(bm + aR) * K2 + k2o + aQ4);
            nal = *reinterpret_cast<const uint4*>(Al + (size_t)(bm + aR) * K2 + k2o + aQ4);
            nbh = *reinterpret_cast<const uint2*>(Bh + (size_t)(k2o + bK2) * N + bn + bC);
            nbl = *reinterpret_cast<const uint2*>(Bl + (size_t)(k2o + bK2) * N + bn + bC);
        }

        const uint32_t* ahs = Ahs[buf];
        const uint32_t* als = Als[buf];
        const uint32_t* bhs = Bhs[buf];
        const uint32_t* bls = Bls[buf];

        uint32_t ah[2][4], al[2][4];
#pragma unroll
        for (int mf = 0; mf < 2; mf++) {
            const int m = warpM * 32 + mf * 16 + g;
            ah[mf][0] = ahs[tq*HASTR + m];
            ah[mf][1] = ahs[tq*HASTR + m + 8];
            ah[mf][2] = ahs[(tq+4)*HASTR + m];
            ah[mf][3] = ahs[(tq+4)*HASTR + m + 8];
            al[mf][0] = als[tq*HASTR + m];
            al[mf][1] = als[tq*HASTR + m + 8];
            al[mf][2] = als[(tq+4)*HASTR + m];
            al[mf][3] = als[(tq+4)*HASTR + m + 8];
        }
        uint32_t bh[4][2], bl[4][2];
#pragma unroll
        for (int nf = 0; nf < 4; nf++) {
            const int n = warpN * 32 + nf * 8 + g;
            bh[nf][0] = bhs[tq*HBSTR + n];
            bh[nf][1] = bhs[(tq+4)*HBSTR + n];
            bl[nf][0] = bls[tq*HBSTR + n];
            bl[nf][1] = bls[(tq+4)*HBSTR + n];
        }
#pragma unroll
        for (int mf = 0; mf < 2; mf++)
#pragma unroll
            for (int nf = 0; nf < 4; nf++) mma_bf16(acc[mf][nf], ah[mf], bh[nf]);
#pragma unroll
        for (int mf = 0; mf < 2; mf++)
#pragma unroll
            for (int nf = 0; nf < 4; nf++) mma_bf16(acc[mf][nf], al[mf], bh[nf]);
#pragma unroll
        for (int mf = 0; mf < 2; mf++)
#pragma unroll
            for (int nf = 0; nf < 4; nf++) mma_bf16(acc[mf][nf], ah[mf], bl[nf]);

        if (more) {
            const int nbuf = buf ^ 1;
            Ahs[nbuf][(aQ4+0)*HASTR + aR] = nah.x; Ahs[nbuf][(aQ4+1)*HASTR + aR] = nah.y;
            Ahs[nbuf][(aQ4+2)*HASTR + aR] = nah.z; Ahs[nbuf][(aQ4+3)*HASTR + aR] = nah.w;
            Als[nbuf][(aQ4+0)*HASTR + aR] = nal.x; Als[nbuf][(aQ4+1)*HASTR + aR] = nal.y;
            Als[nbuf][(aQ4+2)*HASTR + aR] = nal.z; Als[nbuf][(aQ4+3)*HASTR + aR] = nal.w;
            *reinterpret_cast<uint2*>(&Bhs[nbuf][bK2*HBSTR + bC]) = nbh;
            *reinterpret_cast<uint2*>(&Bls[nbuf][bK2*HBSTR + bC]) = nbl;
        }
        __syncthreads();
    }

#pragma unroll
    for (int mf = 0; mf < 2; mf++) {
#pragma unroll
        for (int nf = 0; nf < 4; nf++) {
            const int r0 = bm + warpM * 32 + mf * 16 + g;
            const int c0 = bn + warpN * 32 + nf * 8 + tq * 2;
            float2 bv = *reinterpret_cast<const float2*>(bias + c0);
            float2 o0 = make_float2(acc[mf][nf][0] + bv.x, acc[mf][nf][1] + bv.y);
            float2 o1 = make_float2(acc[mf][nf][2] + bv.x, acc[mf][nf][3] + bv.y);
            *reinterpret_cast<float2*>(C + (size_t)r0 * ldc + c0)       = o0;
            *reinterpret_cast<float2*>(C + (size_t)(r0 + 8) * ldc + c0) = o1;
        }
    }
}

// ------------- LayerNorm(q,k) + phi softmax + v copy, per (b,n) ----------
__global__ __launch_bounds__(512) void ln_phi_kernel(
    const float* __restrict__ qw, const float* __restrict__ qb,
    const float* __restrict__ kw, const float* __restrict__ kb)
{
    int bn = blockIdx.x;
    int b = bn / Nn, n = bn % Nn;
    int h = threadIdx.x >> 5;
    int lane = threadIdx.x & 31;
    const float* row = g_qkv + (size_t)bn * (3*Cc);
    int d0 = lane, d1 = lane + 32;
    size_t obase = ((size_t)(b*Hh + h) * Nn + n) * Dd;

    // ---- q ----
    {
        float v0 = row[h*Dd + d0], v1 = row[h*Dd + d1];
        float s = v0 + v1;
#pragma unroll
        for (int o = 16; o; o >>= 1) s += __shfl_xor_sync(~0u, s, o);
        float m = s * (1.f/64.f);
        float a0 = v0 - m, a1 = v1 - m;
        float vs = a0*a0 + a1*a1;
#pragma unroll
        for (int o = 16; o; o >>= 1) vs += __shfl_xor_sync(~0u, vs, o);
        float r = rsqrtf(vs * (1.f/64.f) + 1e-6f);
        float y0 = a0*r*qw[d0] + qb[d0];
        float y1 = a1*r*qw[d1] + qb[d1];
        g_q[obase + d0] = y0; g_q[obase + d1] = y1;
        float mx = fmaxf(y0, y1);
#pragma unroll
        for (int o = 16; o; o >>= 1) mx = fmaxf(mx, __shfl_xor_sync(~0u, mx, o));
        float e0 = __expf(y0 - mx), e1 = __expf(y1 - mx);
        float se = e0 + e1;
#pragma unroll
        for (int o = 16; o; o >>= 1) se += __shfl_xor_sync(~0u, se, o);
        float inv = 1.f / se;
        g_pq[obase + d0] = e0*inv; g_pq[obase + d1] = e1*inv;
    }
    // ---- k ----
    {
        float v0 = row[Cc + h*Dd + d0], v1 = row[Cc + h*Dd + d1];
        float s = v0 + v1;
#pragma unroll
        for (int o = 16; o; o >>= 1) s += __shfl_xor_sync(~0u, s, o);
        float m = s * (1.f/64.f);
        float a0 = v0 - m, a1 = v1 - m;
        float vs = a0*a0 + a1*a1;
#pragma unroll
        for (int o = 16; o; o >>= 1) vs += __shfl_xor_sync(~0u, vs, o);
        float r = rsqrtf(vs * (1.f/64.f) + 1e-6f);
        float y0 = a0*r*kw[d0] + kb[d0];
        float y1 = a1*r*kw[d1] + kb[d1];
        g_k[obase + d0] = y0; g_k[obase + d1] = y1;
        float mx = fmaxf(y0, y1);
#pragma unroll
        for (int o = 16; o; o >>= 1) mx = fmaxf(mx, __shfl_xor_sync(~0u, mx, o));
        float e0 = __expf(y0 - mx), e1 = __expf(y1 - mx);
        float se = e0 + e1;
#pragma unroll
        for (int o = 16; o; o >>= 1) se += __shfl_xor_sync(~0u, se, o);
        float inv = 1.f / se;
        g_pk[obase + d0] = e0*inv; g_pk[obase + d1] = e1*inv;
    }
    // ---- v copy ----
    g_v[obase + d0] = row[2*Cc + h*Dd + d0];
    g_v[obase + d1] = row[2*Cc + h*Dd + d1];
}

// ------------- compressed keys: mean pool over BLK=8 ---------------------
__global__ __launch_bounds__(64) void kcmp_kernel()
{
    int bhm = blockIdx.x;
    int d = threadIdx.x;
    int bh = bhm / NBc, m = bhm % NBc;
    const float* kr = g_k + ((size_t)bh*Nn + m*BLKc) * Dd;
    float s = 0.f;
#pragma unroll
    for (int t = 0; t < BLKc; t++) s += kr[t*Dd + d];
    g_kcmp[(size_t)bhm*Dd + d] = s * (1.f/BLKc);
}

// ------------- kv/z partials ----------------------------------------------
__global__ __launch_bounds__(256) void kv_chunk_kernel()
{
    int bh = blockIdx.x;
    int ch = blockIdx.y;
    int tid = threadIdx.x;
    int e = tid & 63;
    int dg = tid >> 6;
    __shared__ float sh[4][128];
    float acc[16];
#pragma unroll
    for (int j = 0; j < 16; j++) acc[j] = 0.f;
    float zacc = 0.f;
    size_t base = (size_t)bh * Nn * Dd;
    const int lr = tid >> 6;
    const int lc = (tid & 63) * 2;
    for (int i0 = 0; i0 < CHLEN; i0 += 4) {
        __syncthreads();
        {
            int n = ch * CHLEN + i0 + lr;
            float2 val;
            if (lc < 64)
                val = *reinterpret_cast<const float2*>(g_pk + base + (size_t)n*Dd + lc);
            else
                val = *reinterpret_cast<const float2*>(g_v + base + (size_t)n*Dd + (lc - 64));
            sh[lr][lc]   = val.x;
            sh[lr][lc+1] = val.y;
        }
        __syncthreads();
#pragma unroll
        for (int r = 0; r < 4; r++) {
            float ve = sh[r][64 + e];
#pragma unroll
            for (int j = 0; j < 16; j++) acc[j] += sh[r][dg*16 + j] * ve;
            if (tid < 64) zacc += sh[r][tid];
        }
    }
    float* out = g_kvp + ((size_t)ch * BHc + bh) * (Dd*Dd);
#pragma unroll
    for (int j = 0; j < 16; j++) out[(dg*16 + j)*Dd + e] = acc[j];
    if (tid < 64) g_zp[((size_t)ch * BHc + bh) * Dd + tid] = zacc;
}

__global__ __launch_bounds__(256) void kv_reduce_kernel()
{
    int idx = blockIdx.x * 256 + threadIdx.x;
    const int KVN = BHc*Dd*Dd;
    const int ZN  = BHc*Dd;
    if (idx < KVN) {
        float s = 0.f;
#pragma unroll
        for (int c = 0; c < NCHUNK; c++) s += g_kvp[(size_t)c*KVN + idx];
        g_kv[idx] = s;
    } else if (idx < KVN + ZN) {
        int z = idx - KVN;
        float s = 0.f;
#pragma unroll
        for (int c = 0; c < NCHUNK; c++) s += g_zp[(size_t)c*ZN + z];
        g_z[z] = s;
    }
}

// ------------- router + top-7 : smem-transposed kcmp ---------------------
#define KCSTR 132
__global__ __launch_bounds__(256) void router_topk_kernel()
{
    __shared__ float kct[Dd * KCSTR];
    int bh = blockIdx.x >> 4;
    int n0 = (blockIdx.x & 15) * 64;
    int tid = threadIdx.x;
    int warp = tid >> 5, lane = tid & 31;

    const float* kc = g_kcmp + (size_t)bh * NBc * Dd;
#pragma unroll
    for (int i = 0; i < 32; i++) {
        int idx = tid + i * 256;
        int blk = idx >> 6, d = idx & 63;
        kct[d * KCSTR + blk] = kc[idx];
    }
    __syncthreads();

    const float scale = 0.125f;
    const float NEGINF = -__int_as_float(0x7f800000);

    for (int qi = 0; qi < 8; qi++) {
        int n = n0 + warp * 8 + qi;
        const float* qrow = g_q + ((size_t)bh*Nn + n) * Dd;
        float q0 = qrow[lane], q1 = qrow[lane + 32];
        float s0 = 0.f, s1 = 0.f, s2 = 0.f, s3 = 0.f;
#pragma unroll
        for (int d = 0; d < 64; d++) {
            float qd = (d < 32) ? __shfl_sync(~0u, q0, d)
                                : __shfl_sync(~0u, q1, d - 32);
            float4 kv4 = *reinterpret_cast<const float4*>(&kct[d * KCSTR + lane * 4]);
            s0 += qd * kv4.x; s1 += qd * kv4.y;
            s2 += qd * kv4.z; s3 += qd * kv4.w;
        }
        s0 *= scale; s1 *= scale; s2 *= scale; s3 *= scale;

        int qidx = bh * Nn + n;
#pragma unroll
        for (int r = 0; r < TOPKc; r++) {
            float bv = s0; int bj = 0;
            if (s1 > bv) { bv = s1; bj = 1; }
            if (s2 > bv) { bv = s2; bj = 2; }
            if (s3 > bv) { bv = s3; bj = 3; }
            int bm = lane * 4 + bj;
#pragma unroll
            for (int o = 16; o; o >>= 1) {
                float ov = __shfl_xor_sync(~0u, bv, o);
                int   om = __shfl_xor_sync(~0u, bm, o);
                if (ov > bv || (ov == bv && om < bm)) { bv = ov; bm = om; }
            }
            if ((bm >> 2) == lane) {
                int j = bm & 3;
                if      (j == 0) s0 = NEGINF;
                else if (j == 1) s1 = NEGINF;
                else if (j == 2) s2 = NEGINF;
                else             s3 = NEGINF;
            }
            if (lane == 0) g_topk[(size_t)qidx*TOPKc + r] = bm;
        }
    }
}

// ------------- fused sparse softmax attention + linear branch ------------
// warp per query; logits via cooperative 16-lane row reads.
__global__ __launch_bounds__(256) void attn_kernel()
{
    int bh = blockIdx.x / (Nn/8);
    int b = bh / Hh, h = bh % Hh;
    int n0 = (blockIdx.x % (Nn/8)) * 8;
    int warp = threadIdx.x >> 5;
    int lane = threadIdx.x & 31;
    int n = n0 + warp;
    __shared__ float sq  [8][64];
    __shared__ float spq [8][64];
    __shared__ float sp  [8][64];
    __shared__ float slog[8][64];
    __shared__ int   sblk[8][8];

    size_t qb = ((size_t)bh*Nn + n) * Dd;
    {
        float2 a = *reinterpret_cast<const float2*>(g_q  + qb + lane*2);
        float2 c = *reinterpret_cast<const float2*>(g_pq + qb + lane*2);
        sq [warp][lane*2] = a.x; sq [warp][lane*2+1] = a.y;
        spq[warp][lane*2] = c.x; spq[warp][lane*2+1] = c.y;
    }
    if (lane < TOPKc) sblk[warp][lane] = g_topk[((size_t)bh*Nn + n)*TOPKc + lane];
    __syncwarp();

    const float scale = 0.125f;
    const int NSEL = TOPKc * BLKc;   // 56
    const float NEGINF = -__int_as_float(0x7f800000);
    const float4* sq4 = reinterpret_cast<const float4*>(sq[warp]);
    const size_t kbase = (size_t)bh * Nn * Dd;
    const int seg = lane & 15;
    float4 qv = sq4[seg];

    // logits: 2 rows per iteration; 16 lanes x float4 per row
#pragma unroll 4
    for (int i = 0; i < NSEL/2; i++) {
        int s = 2*i + (lane >> 4);
        int tok = sblk[warp][s >> 3] * BLKc + (s & 7);
        float4 kv = __ldg(reinterpret_cast<const float4*>(g_k + kbase + (size_t)tok * Dd) + seg);
        float a = qv.x*kv.x + qv.y*kv.y + qv.z*kv.z + qv.w*kv.w;
#pragma unroll
        for (int o = 8; o; o >>= 1) a += __shfl_xor_sync(~0u, a, o);
        if (seg == 0) slog[warp][s] = a;
    }
    __syncwarp();

    float l0 = slog[warp][lane] * scale;
    float l1 = (lane + 32 < NSEL) ? slog[warp][lane + 32] * scale : NEGINF;
    float mx = fmaxf(l0, l1);
#pragma unroll
    for (int o = 16; o; o >>= 1) mx = fmaxf(mx, __shfl_xor_sync(~0u, mx, o));
    float e0 = __expf(l0 - mx);
    float e1 = (lane + 32 < NSEL) ? __expf(l1 - mx) : 0.f;
    float se = e0 + e1;
#pragma unroll
    for (int o = 16; o; o >>= 1) se += __shfl_xor_sync(~0u, se, o);
    float inv = 1.f / se;
    sp[warp][lane]      = e0 * inv;
    sp[warp][lane + 32] = e1 * inv;
    __syncwarp();

    // PV + linear: lane owns dims 2*lane, 2*lane+1
    const int dd = lane * 2;
    float a0 = 0.f, a1 = 0.f;
#pragma unroll 8
    for (int s = 0; s < NSEL; s++) {
        int tok = sblk[warp][s >> 3] * BLKc + (s & 7);
        float2 vv = *reinterpret_cast<const float2*>(g_v + kbase + (size_t)tok * Dd + dd);
        float p = sp[warp][s];
        a0 += p * vv.x;
        a1 += p * vv.y;
    }

    const float* zr = g_z + (size_t)bh * Dd;
    float pq0 = spq[warp][dd], pq1 = spq[warp][dd + 1];
    float t = pq0 * zr[dd] + pq1 * zr[dd + 1];
#pragma unroll
    for (int o = 16; o; o >>= 1) t += __shfl_xor_sync(~0u, t, o);
    float inv_den = 1.f / (t + 1e-6f);
    const float* kvm = g_kv + (size_t)bh * Dd * Dd;
    float n0a = 0.f, n1a = 0.f;
#pragma unroll
    for (int e = 0; e < 64; e++) {
        float pe = spq[warp][e];
        float2 kv2 = *reinterpret_cast<const float2*>(kvm + e*Dd + dd);
        n0a += pe * kv2.x;
        n1a += pe * kv2.y;
    }
    size_t ob = ((size_t)(b*Nn + n)) * Cc + h*Dd + dd;
    float2 outv = make_float2(a0 + n0a * inv_den, a1 + n1a * inv_den);
    *reinterpret_cast<float2*>(g_attn + ob) = outv;
}

// ---------------------------------------------------------------------------
extern "C" void kernel_launch(void* const* d_in, const int* in_sizes, int n_in,
                              void* d_out, int out_size)
{
    const float* x      = (const float*)d_in[0];
    const float* w_qkv  = (const float*)d_in[1];
    const float* b_qkv  = (const float*)d_in[2];
    const float* qw     = (const float*)d_in[3];
    const float* qb     = (const float*)d_in[4];
    const float* kw     = (const float*)d_in[5];
    const float* kb     = (const float*)d_in[6];
    const float* w_proj = (const float*)d_in[7];
    const float* b_proj = (const float*)d_in[8];
    float* out = (float*)d_out;

    void *p_qkv = nullptr, *p_attn = nullptr;
    void *p_xh, *p_xl, *p_ah, *p_al, *p_wvh, *p_wvl, *p_wph, *p_wpl;
    cudaGetSymbolAddress(&p_qkv,  g_qkv);
    cudaGetSymbolAddress(&p_attn, g_attn);
    cudaGetSymbolAddress(&p_xh, g_xh);  cudaGetSymbolAddress(&p_xl, g_xl);
    cudaGetSymbolAddress(&p_ah, g_ah);  cudaGetSymbolAddress(&p_al, g_al);
    cudaGetSymbolAddress(&p_wvh, g_wvh); cudaGetSymbolAddress(&p_wvl, g_wvl);
    cudaGetSymbolAddress(&p_wph, g_wph); cudaGetSymbolAddress(&p_wpl, g_wpl);

    const int M = Bb*Nn;               // 2048

    // 0) bf16 splits of x, w_qkv v-slice, w_proj
    split_a_kernel<<<(M*K2c)/256, 256>>>(x, (uint32_t*)p_xh, (uint32_t*)p_xl, M*K2c);
    split_b_kernel<<<(K2c*Cc)/256, 256>>>(w_qkv + 2*Cc, (uint32_t*)p_wvh, (uint32_t*)p_wvl, 3*Cc);
    split_b_kernel<<<(K2c*Cc)/256, 256>>>(w_proj, (uint32_t*)p_wph, (uint32_t*)p_wpl, Cc);

    // 1a) q,k columns: 3xTF32   qkv[:, 0:2048]
    {
        dim3 grid((2*Cc)/GBN, M/GBM);
        gemm_tf32_kernel<<<grid, 256>>>(x, w_qkv, b_qkv, (float*)p_qkv,
                                        M, Cc, 3*Cc, 3*Cc);
    }
    // 1b) v columns: pre-split 3xbf16  qkv[:, 2048:3072]
    {
        dim3 grid(Cc/GBN, M/GBM);
        gemm_bf16_pre_kernel<<<grid, 256>>>((const uint32_t*)p_xh, (const uint32_t*)p_xl,
                                            (const uint32_t*)p_wvh, (const uint32_t*)p_wvl,
                                            b_qkv + 2*Cc, (float*)p_qkv + 2*Cc,
                                            K2c, Cc, 3*Cc);
    }
    // 2) layernorm + phi + split heads
    ln_phi_kernel<<<Bb*Nn, 512>>>(qw, qb, kw, kb);
    // 3) compressed keys
    kcmp_kernel<<<BHc*NBc, 64>>>();
    // 4) kv / z
    {
        dim3 grid(BHc, NCHUNK);
        kv_chunk_kernel<<<grid, 256>>>();
        int total = BHc*Dd*Dd + BHc*Dd;
        kv_reduce_kernel<<<(total + 255)/256, 256>>>();
    }
    // 5) router + topk
    router_topk_kernel<<<BHc*(Nn/64), 256>>>();
    // 6) sparse + linear attention
    attn_kernel<<<BHc*(Nn/8), 256>>>();
    // 7) split attn, then proj GEMM (3xbf16)
    split_a_kernel<<<(M*K2c)/256, 256>>>((const float*)p_attn,
                                         (uint32_t*)p_ah, (uint32_t*)p_al, M*K2c);
    {
        dim3 grid(Cc/GBN, M/GBM);
        gemm_bf16_pre_kernel<<<grid, 256>>>((const uint32_t*)p_ah, (const uint32_t*)p_al,
                                            (const uint32_t*)p_wph, (const uint32_t*)p_wpl,
                                            b_proj, out, K2c, Cc, Cc);
    }
    (void)in_sizes; (void)n_in; (void)out_size;
}